// round 1
// baseline (speedup 1.0000x reference)
#include <cuda_runtime.h>
#include <cuda_bf16.h>
#include <math.h>

// Shapes (fixed by the problem)
#define NPTS  32768
#define CIN   32
#define FC0   256
#define KCH   1024
#define BSEG  16
#define BN_EPS 1e-5f

// ---------------- scratch (device globals; no allocations allowed) ----------
__device__ float g_att1[(size_t)NPTS * FC0];          // 33.5 MB
__device__ float g_e[(size_t)NPTS * KCH];             // 134 MB  exp(relu(bn(.)))
__device__ float g_pooled[(size_t)BSEG * KCH * CIN];  // 2 MB    flattened [B, K*C]
__device__ float g_outraw[BSEG * FC0];                // FC accumulator
__device__ int   g_offsets[BSEG + 1];

// ---------------- prep: segment offsets + zero FC accumulator ---------------
__global__ void prep_kernel(const int* __restrict__ length) {
    int t = threadIdx.x;
    for (int i = t; i < BSEG * FC0; i += 256) g_outraw[i] = 0.0f;
    if (t == 0) {
        int s = 0;
        for (int b = 0; b < BSEG; ++b) { g_offsets[b] = s; s += length[b]; }
        g_offsets[BSEG] = s;
    }
}

// ---------------- GEMM1: att1 = relu(bn1(x @ w1^T + b1))  [N,32]->[N,256] ----
__global__ void __launch_bounds__(256) gemm1_kernel(
    const float* __restrict__ x,  const float* __restrict__ w1,
    const float* __restrict__ b1, const float* __restrict__ g1,
    const float* __restrict__ be1,const float* __restrict__ m1,
    const float* __restrict__ v1)
{
    __shared__ float sx[64][33];
    int n0 = blockIdx.x * 64;
    int j  = threadIdx.x;            // output channel 0..255

    // per-thread weight row in registers
    float w[32];
    const float4* w4 = (const float4*)w1;
#pragma unroll
    for (int k2 = 0; k2 < 8; ++k2) {
        float4 v = w4[j * 8 + k2];
        w[4*k2+0] = v.x; w[4*k2+1] = v.y; w[4*k2+2] = v.z; w[4*k2+3] = v.w;
    }
    // stage 64 input rows
#pragma unroll
    for (int it = 0; it < 8; ++it) {
        int idx = threadIdx.x + 256 * it;      // 0..2047
        int r = idx >> 5, c = idx & 31;
        sx[r][c] = x[(size_t)(n0 + r) * CIN + c];
    }
    __syncthreads();

    float sc   = g1[j] * rsqrtf(v1[j] + BN_EPS);
    float bias = (b1[j] - m1[j]) * sc + be1[j];

    for (int r = 0; r < 64; ++r) {
        float dot = 0.0f;
#pragma unroll
        for (int k = 0; k < 32; ++k) dot = fmaf(sx[r][k], w[k], dot);
        float t = fmaf(dot, sc, bias);
        g_att1[(size_t)(n0 + r) * FC0 + j] = t > 0.0f ? t : 0.0f;
    }
}

// ---------------- GEMM2 + epilogue: e = exp(relu(bn2(att1 @ w2^T + b2))) ----
// [N,256] x [1024,256]^T -> [N,1024], 128x128 tile, 8x8 per thread, FFMA.
__global__ void __launch_bounds__(256) gemm2_kernel(
    const float* __restrict__ W,   // w2 [1024,256]
    const float* __restrict__ b2,  const float* __restrict__ g2,
    const float* __restrict__ be2, const float* __restrict__ m2,
    const float* __restrict__ v2)
{
    __shared__ float As[128][33];   // As[n][k]
    __shared__ float Bs[32][132];   // Bs[k][j]

    int n0 = blockIdx.y * 128;
    int j0 = blockIdx.x * 128;
    int tid = threadIdx.x;
    int tx = tid & 15, ty = tid >> 4;

    float acc[8][8];
#pragma unroll
    for (int i = 0; i < 8; ++i)
#pragma unroll
        for (int jj = 0; jj < 8; ++jj) acc[i][jj] = 0.0f;

    const float4* A4 = (const float4*)g_att1;
    const float4* W4 = (const float4*)W;

    for (int k0 = 0; k0 < 256; k0 += 32) {
#pragma unroll
        for (int it = 0; it < 4; ++it) {
            int idx = tid + 256 * it;          // 0..1023 float4s
            int r = idx >> 3, c4 = idx & 7;
            float4 v = A4[(size_t)(n0 + r) * 64 + (k0 >> 2) + c4];
            As[r][c4*4+0] = v.x; As[r][c4*4+1] = v.y;
            As[r][c4*4+2] = v.z; As[r][c4*4+3] = v.w;
        }
#pragma unroll
        for (int it = 0; it < 4; ++it) {
            int idx = tid + 256 * it;
            int r = idx >> 3, c4 = idx & 7;
            float4 v = W4[(size_t)(j0 + r) * 64 + (k0 >> 2) + c4];
            Bs[c4*4+0][r] = v.x; Bs[c4*4+1][r] = v.y;
            Bs[c4*4+2][r] = v.z; Bs[c4*4+3][r] = v.w;
        }
        __syncthreads();

#pragma unroll
        for (int kk = 0; kk < 32; ++kk) {
            float a[8], bb[8];
#pragma unroll
            for (int i = 0; i < 8; ++i) a[i] = As[ty*8 + i][kk];
            float4 bv0 = *(const float4*)&Bs[kk][tx*8];
            float4 bv1 = *(const float4*)&Bs[kk][tx*8 + 4];
            bb[0]=bv0.x; bb[1]=bv0.y; bb[2]=bv0.z; bb[3]=bv0.w;
            bb[4]=bv1.x; bb[5]=bv1.y; bb[6]=bv1.z; bb[7]=bv1.w;
#pragma unroll
            for (int i = 0; i < 8; ++i)
#pragma unroll
                for (int jj = 0; jj < 8; ++jj)
                    acc[i][jj] = fmaf(a[i], bb[jj], acc[i][jj]);
        }
        __syncthreads();
    }

    // epilogue: BN per column, relu, exp; softmax max-shift is skipped (exact,
    // att is small post-BN so exp cannot overflow fp32)
    float sc[8], bias[8];
#pragma unroll
    for (int jj = 0; jj < 8; ++jj) {
        int j = j0 + tx*8 + jj;
        sc[jj]   = g2[j] * rsqrtf(v2[j] + BN_EPS);
        bias[jj] = (b2[j] - m2[j]) * sc[jj] + be2[j];
    }
#pragma unroll
    for (int i = 0; i < 8; ++i) {
        int row = n0 + ty*8 + i;
        float o[8];
#pragma unroll
        for (int jj = 0; jj < 8; ++jj) {
            float t = fmaf(acc[i][jj], sc[jj], bias[jj]);
            o[jj] = (t > 0.0f) ? __expf(t) : 1.0f;   // exp(relu(t))
        }
        float4* dst = (float4*)&g_e[(size_t)row * KCH + j0 + tx*8];
        dst[0] = make_float4(o[0], o[1], o[2], o[3]);
        dst[1] = make_float4(o[4], o[5], o[6], o[7]);
    }
}

// ---------------- pooling: pooled[b, k*32+c] = sum_n e*x / (sum_n e * len) --
// block = (kt, b): 32 channels x one segment. Segment-sum fused (x aug by 1).
__global__ void __launch_bounds__(256) pool_kernel(
    const float* __restrict__ x, const int* __restrict__ length)
{
    int kt = blockIdx.x;            // 0..31
    int b  = blockIdx.y;            // 0..15
    int start = g_offsets[b], end = g_offsets[b + 1];

    __shared__ float se[64][32];
    __shared__ float sx[64][32];
    __shared__ float sk[32];

    int k  = threadIdx.x >> 3;      // local channel 0..31
    int cg = threadIdx.x & 7;       // x-col group: handles c = 4*cg .. 4*cg+3

    float4 acc = make_float4(0.f, 0.f, 0.f, 0.f);
    float  sacc = 0.0f;

    for (int r0 = start; r0 < end; r0 += 64) {
        int nr = min(64, end - r0);
#pragma unroll
        for (int it = 0; it < 8; ++it) {
            int idx = threadIdx.x + 256 * it;    // 0..2047
            int r = idx >> 5, c = idx & 31;
            if (r < nr) {
                se[r][c] = g_e[(size_t)(r0 + r) * KCH + kt*32 + c];
                sx[r][c] = x[(size_t)(r0 + r) * CIN + c];
            }
        }
        __syncthreads();
        for (int r = 0; r < nr; ++r) {
            float ev = se[r][k];
            float4 xv = *(const float4*)&sx[r][cg * 4];
            acc.x = fmaf(ev, xv.x, acc.x);
            acc.y = fmaf(ev, xv.y, acc.y);
            acc.z = fmaf(ev, xv.z, acc.z);
            acc.w = fmaf(ev, xv.w, acc.w);
            if (cg == 0) sacc += ev;
        }
        __syncthreads();
    }

    if (cg == 0) sk[k] = sacc;
    __syncthreads();
    float inv = 1.0f / (sk[k] * (float)length[b]);

    int kglob = kt*32 + k;
    float4* dst = (float4*)&g_pooled[((size_t)b * KCH + kglob) * CIN + cg*4];
    *dst = make_float4(acc.x*inv, acc.y*inv, acc.z*inv, acc.w*inv);
}

// ---------------- FC: out_raw[b,j] += pooled[b,:] . fcw[j,:]  (split-K) -----
__global__ void __launch_bounds__(256) fc_kernel(const float* __restrict__ fcw)
{
    int warp = threadIdx.x >> 5, lane = threadIdx.x & 31;
    int j  = blockIdx.x * 8 + warp;          // 0..255
    int i0 = blockIdx.y * 2048;              // 16 chunks over 32768

    float acc[BSEG];
#pragma unroll
    for (int b = 0; b < BSEG; ++b) acc[b] = 0.0f;

    const float4* fw4 = (const float4*)(fcw + (size_t)j * (KCH*CIN) + i0);
#pragma unroll 4
    for (int it = 0; it < 16; ++it) {
        int i4 = it * 32 + lane;             // 512 float4 = 2048 floats
        float4 f = fw4[i4];
#pragma unroll
        for (int b = 0; b < BSEG; ++b) {
            float4 p = ((const float4*)(g_pooled + (size_t)b * (KCH*CIN) + i0))[i4];
            acc[b] += f.x*p.x + f.y*p.y + f.z*p.z + f.w*p.w;
        }
    }
#pragma unroll
    for (int b = 0; b < BSEG; ++b) {
        float v = acc[b];
#pragma unroll
        for (int s = 16; s > 0; s >>= 1) v += __shfl_xor_sync(0xffffffffu, v, s);
        if (lane == 0) atomicAdd(&g_outraw[b * FC0 + j], v);
    }
}

// ---------------- final: BN3 + row L2-normalize -> d_out [16,256] -----------
__global__ void final_kernel(
    const float* __restrict__ fcb, const float* __restrict__ g3,
    const float* __restrict__ be3, const float* __restrict__ m3,
    const float* __restrict__ v3,  float* __restrict__ out)
{
    int b = blockIdx.x, j = threadIdx.x;
    float sc = g3[j] * rsqrtf(v3[j] + BN_EPS);
    float r  = fmaf(g_outraw[b * FC0 + j] + fcb[j] - m3[j], sc, be3[j]);

    __shared__ float red[256];
    red[j] = r * r;
    __syncthreads();
    for (int s = 128; s > 0; s >>= 1) {
        if (j < s) red[j] += red[j + s];
        __syncthreads();
    }
    float inv = 1.0f / fmaxf(sqrtf(red[0]), 1e-12f);
    out[b * FC0 + j] = r * inv;
}

// ---------------- launch ----------------------------------------------------
extern "C" void kernel_launch(void* const* d_in, const int* in_sizes, int n_in,
                              void* d_out, int out_size)
{
    const float* x      = (const float*)d_in[0];
    const int*   length = (const int*)  d_in[1];
    const float* w1  = (const float*)d_in[2];
    const float* b1  = (const float*)d_in[3];
    const float* g1  = (const float*)d_in[4];
    const float* be1 = (const float*)d_in[5];
    const float* m1  = (const float*)d_in[6];
    const float* v1  = (const float*)d_in[7];
    const float* w2  = (const float*)d_in[8];
    const float* b2  = (const float*)d_in[9];
    const float* g2  = (const float*)d_in[10];
    const float* be2 = (const float*)d_in[11];
    const float* m2  = (const float*)d_in[12];
    const float* v2  = (const float*)d_in[13];
    const float* fcw = (const float*)d_in[14];
    const float* fcb = (const float*)d_in[15];
    const float* g3  = (const float*)d_in[16];
    const float* be3 = (const float*)d_in[17];
    const float* m3  = (const float*)d_in[18];
    const float* v3  = (const float*)d_in[19];
    float* out = (float*)d_out;

    prep_kernel<<<1, 256>>>(length);
    gemm1_kernel<<<NPTS / 64, 256>>>(x, w1, b1, g1, be1, m1, v1);
    gemm2_kernel<<<dim3(KCH / 128, NPTS / 128), 256>>>(w2, b2, g2, be2, m2, v2);
    pool_kernel<<<dim3(KCH / 32, BSEG), 256>>>(x, length);
    fc_kernel<<<dim3(FC0 / 8, 16), 256>>>(fcw);
    final_kernel<<<BSEG, 256>>>(fcb, g3, be3, m3, v3, out);
}

// round 3
// speedup vs baseline: 2.8652x; 2.8652x over previous
#include <cuda_runtime.h>
#include <cuda_fp16.h>
#include <math.h>
#include <stdint.h>

// Shapes (fixed by the problem)
#define NPTS  32768
#define CIN   32
#define FC0V  256
#define KCH   1024
#define BSEG  16
#define BN_EPS 1e-5f
#define LOG2E_F 1.44269504088896340736f

// ---------------- scratch (device globals; no allocations allowed) ----------
__device__ __half g_att1h[(size_t)NPTS * FC0V];        // 16 MB  fp16 att1
__device__ __half g_w2h[(size_t)KCH * FC0V];           // 512 KB fp16 w2
__device__ __half g_e[(size_t)NPTS * KCH];             // 67 MB  fp16 exp(relu(bn))
__device__ float  g_sc2[KCH];
__device__ float  g_bias2[KCH];
__device__ float  g_poolsum[(size_t)BSEG * KCH * CIN]; // 2 MB
__device__ float  g_esum[BSEG * KCH];
__device__ float  g_pooled[(size_t)BSEG * KCH * CIN];  // 2 MB
__device__ float  g_outraw[BSEG * FC0V];
__device__ int    g_offsets[BSEG + 1];

// ---------------- helpers ----------------------------------------------------
__device__ __forceinline__ uint32_t smem_u32(const void* p) {
    uint32_t a;
    asm("{ .reg .u64 t; cvta.to.shared.u64 t, %1; cvt.u32.u64 %0, t; }"
        : "=r"(a) : "l"(p));
    return a;
}

#define LDMATRIX_X4(r, addr) \
    asm volatile("ldmatrix.sync.aligned.m8n8.x4.shared.b16 {%0,%1,%2,%3}, [%4];" \
        : "=r"((r)[0]), "=r"((r)[1]), "=r"((r)[2]), "=r"((r)[3]) : "r"(addr))

#define MMA_16816(d, a, b0, b1) \
    asm volatile("mma.sync.aligned.m16n8k16.row.col.f32.f16.f16.f32 " \
        "{%0,%1,%2,%3}, {%4,%5,%6,%7}, {%8,%9}, {%0,%1,%2,%3};" \
        : "+f"((d)[0]), "+f"((d)[1]), "+f"((d)[2]), "+f"((d)[3]) \
        : "r"((a)[0]), "r"((a)[1]), "r"((a)[2]), "r"((a)[3]), "r"(b0), "r"(b1))

// ---------------- prep -------------------------------------------------------
__global__ void prep_kernel(const int* __restrict__ length, const float* __restrict__ w2,
                            const float* __restrict__ b2, const float* __restrict__ g2,
                            const float* __restrict__ be2, const float* __restrict__ m2,
                            const float* __restrict__ v2) {
    int gid = blockIdx.x * blockDim.x + threadIdx.x;
    int stride = gridDim.x * blockDim.x;
    for (int i = gid; i < BSEG * KCH * CIN; i += stride) g_poolsum[i] = 0.0f;
    for (int i = gid; i < BSEG * KCH; i += stride)       g_esum[i] = 0.0f;
    for (int i = gid; i < BSEG * FC0V; i += stride)      g_outraw[i] = 0.0f;
    for (int i = gid; i < KCH * FC0V; i += stride)       g_w2h[i] = __float2half(w2[i]);
    for (int j = gid; j < KCH; j += stride) {
        float sc = g2[j] * rsqrtf(v2[j] + BN_EPS);
        g_sc2[j]   = sc * LOG2E_F;
        g_bias2[j] = ((b2[j] - m2[j]) * sc + be2[j]) * LOG2E_F;
    }
    if (gid == 0) {
        int s = 0;
        for (int b = 0; b < BSEG; ++b) { g_offsets[b] = s; s += length[b]; }
        g_offsets[BSEG] = s;
    }
}

// ---------------- GEMM1: att1h = fp16(relu(bn1(x @ w1^T + b1))) --------------
__global__ void __launch_bounds__(256) gemm1_kernel(
    const float* __restrict__ x,  const float* __restrict__ w1,
    const float* __restrict__ b1, const float* __restrict__ g1,
    const float* __restrict__ be1,const float* __restrict__ m1,
    const float* __restrict__ v1)
{
    __shared__ float sx[64][33];
    int n0 = blockIdx.x * 64;
    int j  = threadIdx.x;

    float w[32];
    const float4* w4 = (const float4*)w1;
#pragma unroll
    for (int k2 = 0; k2 < 8; ++k2) {
        float4 v = w4[j * 8 + k2];
        w[4*k2+0] = v.x; w[4*k2+1] = v.y; w[4*k2+2] = v.z; w[4*k2+3] = v.w;
    }
#pragma unroll
    for (int it = 0; it < 8; ++it) {
        int idx = threadIdx.x + 256 * it;
        int r = idx >> 5, c = idx & 31;
        sx[r][c] = x[(size_t)(n0 + r) * CIN + c];
    }
    __syncthreads();

    float sc   = g1[j] * rsqrtf(v1[j] + BN_EPS);
    float bias = (b1[j] - m1[j]) * sc + be1[j];

    for (int r = 0; r < 64; ++r) {
        float dot = 0.0f;
#pragma unroll
        for (int k = 0; k < 32; ++k) dot = fmaf(sx[r][k], w[k], dot);
        float t = fmaf(dot, sc, bias);
        g_att1h[(size_t)(n0 + r) * FC0V + j] = __float2half(t > 0.0f ? t : 0.0f);
    }
}

// ---------------- GEMM2 via HMMA mma.sync: e = fp16(exp(relu(bn2(.)))) -------
// C[128 rows x 128 cols] per CTA; 8 warps (2m x 4n), warp tile 64x32.
// K=256 staged through swizzled SMEM in 64-wide chunks.
__global__ void __launch_bounds__(256) gemm2_kernel()
{
    __shared__ __half As[128 * 64];
    __shared__ __half Bs[128 * 64];
    __shared__ float  s_sc[128], s_bias[128];

    int tid = threadIdx.x, lane = tid & 31, wid = tid >> 5;
    int n0 = blockIdx.x * 128;
    int j0 = blockIdx.y * 128;

    if (tid < 128) { s_sc[tid] = g_sc2[j0 + tid]; s_bias[tid] = g_bias2[j0 + tid]; }

    uint32_t aBase = smem_u32(As), bBase = smem_u32(Bs);
    int warp_m = (wid & 1) * 64;
    int warp_n = (wid >> 1) * 32;

    float acc[4][4][4];
#pragma unroll
    for (int mf = 0; mf < 4; ++mf)
#pragma unroll
        for (int n8 = 0; n8 < 4; ++n8)
#pragma unroll
            for (int q = 0; q < 4; ++q) acc[mf][n8][q] = 0.0f;

    int lrow  = lane & 15;
    int lkoff = (lane >> 4) * 16;     // 8 halves = 16 bytes

    for (int kc = 0; kc < 4; ++kc) {
        int k0 = kc * 64;
        // stage A and B chunks: 128 rows x 64 halves (128B rows), SW128 swizzle
#pragma unroll
        for (int it = 0; it < 4; ++it) {
            int idx = tid + 256 * it;              // 0..1023
            int row = idx >> 3, ch = idx & 7;
            uint32_t off = (uint32_t)(row * 128 + ch * 16);
            uint32_t swz = off ^ ((off >> 3) & 0x70);
            *(uint4*)((char*)As + swz) =
                *(const uint4*)(g_att1h + (size_t)(n0 + row) * FC0V + k0 + ch * 8);
            *(uint4*)((char*)Bs + swz) =
                *(const uint4*)(g_w2h + (size_t)(j0 + row) * FC0V + k0 + ch * 8);
        }
        __syncthreads();

#pragma unroll
        for (int ks = 0; ks < 4; ++ks) {
            int kbyte = ks * 32 + lkoff;           // 16 halves per k16 step
            uint32_t a[4][4];
#pragma unroll
            for (int mf = 0; mf < 4; ++mf) {
                uint32_t off = (uint32_t)((warp_m + mf * 16 + lrow) * 128);
                uint32_t addr = aBase + ((off + kbyte) ^ ((off >> 3) & 0x70));
                LDMATRIX_X4(a[mf], addr);
            }
            uint32_t bm[2][4];
#pragma unroll
            for (int nf = 0; nf < 2; ++nf) {
                uint32_t off = (uint32_t)((warp_n + nf * 16 + lrow) * 128);
                uint32_t addr = bBase + ((off + kbyte) ^ ((off >> 3) & 0x70));
                LDMATRIX_X4(bm[nf], addr);
            }
#pragma unroll
            for (int mf = 0; mf < 4; ++mf)
#pragma unroll
                for (int n8 = 0; n8 < 4; ++n8)
                    MMA_16816(acc[mf][n8], a[mf],
                              bm[n8 >> 1][n8 & 1], bm[n8 >> 1][(n8 & 1) + 2]);
        }
        __syncthreads();
    }

    // epilogue: BN (log2-folded) + relu + exp2, store fp16
    int qrow = lane >> 2, qcol = (lane & 3) * 2;
#pragma unroll
    for (int mf = 0; mf < 4; ++mf) {
#pragma unroll
        for (int n8 = 0; n8 < 4; ++n8) {
            int cloc = warp_n + n8 * 8 + qcol;
            float sc0 = s_sc[cloc],   sc1 = s_sc[cloc + 1];
            float bi0 = s_bias[cloc], bi1 = s_bias[cloc + 1];
#pragma unroll
            for (int h = 0; h < 2; ++h) {
                int row = n0 + warp_m + mf * 16 + qrow + h * 8;
                float t0 = fmaf(acc[mf][n8][h * 2],     sc0, bi0);
                float t1 = fmaf(acc[mf][n8][h * 2 + 1], sc1, bi1);
                float e0 = t0 > 0.0f ? exp2f(t0) : 1.0f;
                float e1 = t1 > 0.0f ? exp2f(t1) : 1.0f;
                *(__half2*)(g_e + (size_t)row * KCH + j0 + cloc) =
                    __floats2half2_rn(e0, e1);
            }
        }
    }
}

// ---------------- pool: poolsum[b,k,c] += sum_n e[n,k]*x[n,c]; esum += e -----
// grid = (32 row-chunks of 1024, 8 k-tiles of 128). 16 fp32 acc per thread.
__global__ void __launch_bounds__(256) pool_kernel(const float* __restrict__ x)
{
    int kt = blockIdx.y;                 // 0..7
    int cs = blockIdx.x * 1024;
    int ce = cs + 1024;

    __shared__ __half se[64][128];
    __shared__ float  sx[64][32];

    int ty = threadIdx.x >> 3;           // 0..31 -> 4 k-channels
    int tx = threadIdx.x & 7;            // 0..7  -> 4 c-columns

    int b = 0;
    while (g_offsets[b + 1] <= cs) ++b;

    int cur = cs;
    while (cur < ce) {
        int send = min(ce, g_offsets[b + 1]);

        float acc[4][4];
        float es[4];
#pragma unroll
        for (int i = 0; i < 4; ++i) {
            es[i] = 0.0f;
#pragma unroll
            for (int c = 0; c < 4; ++c) acc[i][c] = 0.0f;
        }

        for (int r0 = cur; r0 < send; r0 += 64) {
            int nr = min(64, send - r0);
#pragma unroll
            for (int it = 0; it < 4; ++it) {
                int idx = threadIdx.x + 256 * it;
                int r = idx >> 4, c16 = idx & 15;
                if (r < nr)
                    *(uint4*)&se[r][c16 * 8] =
                        *(const uint4*)(g_e + (size_t)(r0 + r) * KCH + kt * 128 + c16 * 8);
            }
#pragma unroll
            for (int it = 0; it < 2; ++it) {
                int idx = threadIdx.x + 256 * it;
                int r = idx >> 3, c4 = idx & 7;
                if (r < nr)
                    *(float4*)&sx[r][c4 * 4] =
                        *(const float4*)(x + (size_t)(r0 + r) * CIN + c4 * 4);
            }
            __syncthreads();

            for (int r = 0; r < nr; ++r) {
                uint2 eu = *(const uint2*)&se[r][ty * 4];
                float2 e01 = __half22float2(*(__half2*)&eu.x);
                float2 e23 = __half22float2(*(__half2*)&eu.y);
                float ev[4] = {e01.x, e01.y, e23.x, e23.y};
                float4 xv = *(const float4*)&sx[r][tx * 4];
#pragma unroll
                for (int i = 0; i < 4; ++i) {
                    acc[i][0] = fmaf(ev[i], xv.x, acc[i][0]);
                    acc[i][1] = fmaf(ev[i], xv.y, acc[i][1]);
                    acc[i][2] = fmaf(ev[i], xv.z, acc[i][2]);
                    acc[i][3] = fmaf(ev[i], xv.w, acc[i][3]);
                }
                if (tx == 0) {
#pragma unroll
                    for (int i = 0; i < 4; ++i) es[i] += ev[i];
                }
            }
            __syncthreads();
        }

        int kbase = kt * 128 + ty * 4;
#pragma unroll
        for (int i = 0; i < 4; ++i) {
#pragma unroll
            for (int c = 0; c < 4; ++c)
                atomicAdd(&g_poolsum[((size_t)b * KCH + kbase + i) * CIN + tx * 4 + c],
                          acc[i][c]);
            if (tx == 0) atomicAdd(&g_esum[b * KCH + kbase + i], es[i]);
        }
        ++b;
        cur = send;
    }
}

// ---------------- normalize: pooled = poolsum / (esum * len) -----------------
__global__ void norm_kernel(const int* __restrict__ length) {
    int idx = blockIdx.x * 256 + threadIdx.x;     // 0 .. 524287
    int k = (idx >> 5) & 1023, b = idx >> 15;
    g_pooled[idx] = g_poolsum[idx] / (g_esum[b * KCH + k] * (float)length[b]);
}

// ---------------- FC: out_raw[b,j] += pooled[b,:] . fcw[j,:]  (split-K) ------
__global__ void __launch_bounds__(256) fc_kernel(const float* __restrict__ fcw)
{
    int warp = threadIdx.x >> 5, lane = threadIdx.x & 31;
    int j  = blockIdx.x * 8 + warp;
    int i0 = blockIdx.y * 2048;

    float acc[BSEG];
#pragma unroll
    for (int b = 0; b < BSEG; ++b) acc[b] = 0.0f;

    const float4* fw4 = (const float4*)(fcw + (size_t)j * (KCH * CIN) + i0);
#pragma unroll 4
    for (int it = 0; it < 16; ++it) {
        int i4 = it * 32 + lane;
        float4 f = fw4[i4];
#pragma unroll
        for (int b = 0; b < BSEG; ++b) {
            float4 p = ((const float4*)(g_pooled + (size_t)b * (KCH * CIN) + i0))[i4];
            acc[b] += f.x * p.x + f.y * p.y + f.z * p.z + f.w * p.w;
        }
    }
#pragma unroll
    for (int b = 0; b < BSEG; ++b) {
        float v = acc[b];
#pragma unroll
        for (int s = 16; s > 0; s >>= 1) v += __shfl_xor_sync(0xffffffffu, v, s);
        if (lane == 0) atomicAdd(&g_outraw[b * FC0V + j], v);
    }
}

// ---------------- final: BN3 + row L2-normalize -> d_out [16,256] ------------
__global__ void final_kernel(
    const float* __restrict__ fcb, const float* __restrict__ g3,
    const float* __restrict__ be3, const float* __restrict__ m3,
    const float* __restrict__ v3,  float* __restrict__ out)
{
    int b = blockIdx.x, j = threadIdx.x;
    float sc = g3[j] * rsqrtf(v3[j] + BN_EPS);
    float r  = fmaf(g_outraw[b * FC0V + j] + fcb[j] - m3[j], sc, be3[j]);

    __shared__ float red[256];
    red[j] = r * r;
    __syncthreads();
    for (int s = 128; s > 0; s >>= 1) {
        if (j < s) red[j] += red[j + s];
        __syncthreads();
    }
    float inv = 1.0f / fmaxf(sqrtf(red[0]), 1e-12f);
    out[b * FC0V + j] = r * inv;
}

// ---------------- launch -----------------------------------------------------
extern "C" void kernel_launch(void* const* d_in, const int* in_sizes, int n_in,
                              void* d_out, int out_size)
{
    const float* x      = (const float*)d_in[0];
    const int*   length = (const int*)  d_in[1];
    const float* w1  = (const float*)d_in[2];
    const float* b1  = (const float*)d_in[3];
    const float* g1  = (const float*)d_in[4];
    const float* be1 = (const float*)d_in[5];
    const float* m1  = (const float*)d_in[6];
    const float* v1  = (const float*)d_in[7];
    const float* w2  = (const float*)d_in[8];
    const float* b2  = (const float*)d_in[9];
    const float* g2  = (const float*)d_in[10];
    const float* be2 = (const float*)d_in[11];
    const float* m2  = (const float*)d_in[12];
    const float* v2  = (const float*)d_in[13];
    const float* fcw = (const float*)d_in[14];
    const float* fcb = (const float*)d_in[15];
    const float* g3  = (const float*)d_in[16];
    const float* be3 = (const float*)d_in[17];
    const float* m3  = (const float*)d_in[18];
    const float* v3  = (const float*)d_in[19];
    float* out = (float*)d_out;

    prep_kernel<<<64, 256>>>(length, w2, b2, g2, be2, m2, v2);
    gemm1_kernel<<<NPTS / 64, 256>>>(x, w1, b1, g1, be1, m1, v1);
    gemm2_kernel<<<dim3(NPTS / 128, KCH / 128), 256>>>();
    pool_kernel<<<dim3(32, 8), 256>>>(x);
    norm_kernel<<<(BSEG * KCH * CIN) / 256, 256>>>(length);
    fc_kernel<<<dim3(FC0V / 8, 16), 256>>>(fcw);
    final_kernel<<<BSEG, 256>>>(fcb, g3, be3, m3, v3, out);
}

// round 4
// speedup vs baseline: 4.0939x; 1.4289x over previous
#include <cuda_runtime.h>
#include <cuda_fp16.h>
#include <math.h>
#include <stdint.h>

// Shapes (fixed by the problem)
#define NPTS  32768
#define CIN   32
#define FC0V  256
#define KCH   1024
#define BSEG  16
#define BN_EPS 1e-5f
#define LOG2E_F 1.44269504088896340736f

// ---------------- scratch (device globals; no allocations allowed) ----------
__device__ __half g_att1h[(size_t)NPTS * FC0V];        // 16 MB  fp16 att1
__device__ __half g_w2h[(size_t)KCH * FC0V];           // 512 KB fp16 w2
__device__ __half g_xh[(size_t)NPTS * 40];             // 2.6 MB fp16 [x | 1 | 0pad]
__device__ __half g_e[(size_t)NPTS * KCH];             // 67 MB  fp16 exp(relu(bn))
__device__ float  g_sc2[KCH];
__device__ float  g_bias2[KCH];
__device__ float  g_poolsum[(size_t)BSEG * KCH * 40];  // 2.6 MB (col 32 = esum)
__device__ float  g_pooled[(size_t)BSEG * KCH * CIN];  // 2 MB
__device__ float  g_outraw[BSEG * FC0V];
__device__ int    g_offsets[BSEG + 1];

// ---------------- helpers ----------------------------------------------------
__device__ __forceinline__ uint32_t smem_u32(const void* p) {
    uint32_t a;
    asm("{ .reg .u64 t; cvta.to.shared.u64 t, %1; cvt.u32.u64 %0, t; }"
        : "=r"(a) : "l"(p));
    return a;
}

#define LDMATRIX_X4(r, addr) \
    asm volatile("ldmatrix.sync.aligned.m8n8.x4.shared.b16 {%0,%1,%2,%3}, [%4];" \
        : "=r"((r)[0]), "=r"((r)[1]), "=r"((r)[2]), "=r"((r)[3]) : "r"(addr))

#define LDMATRIX_X4T(r, addr) \
    asm volatile("ldmatrix.sync.aligned.m8n8.x4.trans.shared.b16 {%0,%1,%2,%3}, [%4];" \
        : "=r"((r)[0]), "=r"((r)[1]), "=r"((r)[2]), "=r"((r)[3]) : "r"(addr))

#define LDMATRIX_X2T(r, addr) \
    asm volatile("ldmatrix.sync.aligned.m8n8.x2.trans.shared.b16 {%0,%1}, [%2];" \
        : "=r"((r)[0]), "=r"((r)[1]) : "r"(addr))

#define MMA_16816(d, a, b0, b1) \
    asm volatile("mma.sync.aligned.m16n8k16.row.col.f32.f16.f16.f32 " \
        "{%0,%1,%2,%3}, {%4,%5,%6,%7}, {%8,%9}, {%0,%1,%2,%3};" \
        : "+f"((d)[0]), "+f"((d)[1]), "+f"((d)[2]), "+f"((d)[3]) \
        : "r"((a)[0]), "r"((a)[1]), "r"((a)[2]), "r"((a)[3]), "r"(b0), "r"(b1))

#define CP_ASYNC16(dst, src) \
    asm volatile("cp.async.cg.shared.global [%0], [%1], 16;" :: "r"(dst), "l"(src))
#define CP_COMMIT() asm volatile("cp.async.commit_group;" ::: "memory")
#define CP_WAIT1()  asm volatile("cp.async.wait_group 1;" ::: "memory")
#define CP_WAIT0()  asm volatile("cp.async.wait_group 0;" ::: "memory")

// ---------------- prep -------------------------------------------------------
__global__ void prep_kernel(const float* __restrict__ x,
                            const int* __restrict__ length, const float* __restrict__ w2,
                            const float* __restrict__ b2, const float* __restrict__ g2,
                            const float* __restrict__ be2, const float* __restrict__ m2,
                            const float* __restrict__ v2) {
    int gid = blockIdx.x * blockDim.x + threadIdx.x;
    int stride = gridDim.x * blockDim.x;
    for (int i = gid; i < BSEG * KCH * 40; i += stride) g_poolsum[i] = 0.0f;
    for (int i = gid; i < BSEG * FC0V; i += stride)     g_outraw[i] = 0.0f;
    for (int i = gid; i < KCH * FC0V; i += stride)      g_w2h[i] = __float2half(w2[i]);
    for (int n = gid; n < NPTS; n += stride) {
        __half* dst = g_xh + (size_t)n * 40;
#pragma unroll
        for (int c = 0; c < 32; ++c) dst[c] = __float2half(x[(size_t)n * CIN + c]);
        dst[32] = __float2half(1.0f);
#pragma unroll
        for (int c = 33; c < 40; ++c) dst[c] = __float2half(0.0f);
    }
    for (int j = gid; j < KCH; j += stride) {
        float sc = g2[j] * rsqrtf(v2[j] + BN_EPS);
        g_sc2[j]   = sc * LOG2E_F;
        g_bias2[j] = ((b2[j] - m2[j]) * sc + be2[j]) * LOG2E_F;
    }
    if (gid == 0) {
        int s = 0;
        for (int b = 0; b < BSEG; ++b) { g_offsets[b] = s; s += length[b]; }
        g_offsets[BSEG] = s;
    }
}

// ---------------- GEMM1: att1h = fp16(relu(bn1(x @ w1^T + b1))) --------------
__global__ void __launch_bounds__(256) gemm1_kernel(
    const float* __restrict__ x,  const float* __restrict__ w1,
    const float* __restrict__ b1, const float* __restrict__ g1,
    const float* __restrict__ be1,const float* __restrict__ m1,
    const float* __restrict__ v1)
{
    __shared__ float sx[64][33];
    int n0 = blockIdx.x * 64;
    int j  = threadIdx.x;

    float w[32];
    const float4* w4 = (const float4*)w1;
#pragma unroll
    for (int k2 = 0; k2 < 8; ++k2) {
        float4 v = w4[j * 8 + k2];
        w[4*k2+0] = v.x; w[4*k2+1] = v.y; w[4*k2+2] = v.z; w[4*k2+3] = v.w;
    }
#pragma unroll
    for (int it = 0; it < 8; ++it) {
        int idx = threadIdx.x + 256 * it;
        int r = idx >> 5, c = idx & 31;
        sx[r][c] = x[(size_t)(n0 + r) * CIN + c];
    }
    __syncthreads();

    float sc   = g1[j] * rsqrtf(v1[j] + BN_EPS);
    float bias = (b1[j] - m1[j]) * sc + be1[j];

    for (int r = 0; r < 64; ++r) {
        float dot = 0.0f;
#pragma unroll
        for (int k = 0; k < 32; ++k) dot = fmaf(sx[r][k], w[k], dot);
        float t = fmaf(dot, sc, bias);
        g_att1h[(size_t)(n0 + r) * FC0V + j] = __float2half(t > 0.0f ? t : 0.0f);
    }
}

// ---------------- GEMM2 (HMMA, cp.async double-buffered) ---------------------
// C[128 x 128] per CTA; 8 warps (2m x 4n), warp tile 64x32; K=256 in 4 chunks.
// dyn smem: A0@0 A1@16K B0@32K B1@48K sc@64K bias@64K+512   (66,560 B)
__global__ void __launch_bounds__(256) gemm2_kernel()
{
    extern __shared__ char dyn[];
    float* s_sc   = (float*)(dyn + 65536);
    float* s_bias = (float*)(dyn + 66048);

    int tid = threadIdx.x, lane = tid & 31, wid = tid >> 5;
    int n0 = blockIdx.x * 128;
    int j0 = blockIdx.y * 128;

    if (tid < 128) { s_sc[tid] = g_sc2[j0 + tid]; s_bias[tid] = g_bias2[j0 + tid]; }

    uint32_t aBase = smem_u32(dyn);
    uint32_t bBase = aBase + 32768;
    int warp_m = (wid & 1) * 64;
    int warp_n = (wid >> 1) * 32;

    float acc[4][4][4];
#pragma unroll
    for (int mf = 0; mf < 4; ++mf)
#pragma unroll
        for (int n8 = 0; n8 < 4; ++n8)
#pragma unroll
            for (int q = 0; q < 4; ++q) acc[mf][n8][q] = 0.0f;

    // stage chunk kc into buffer d via cp.async (128 rows x 64 halves each)
    auto stage = [&](int kc, int d) {
#pragma unroll
        for (int it = 0; it < 4; ++it) {
            int idx = tid + 256 * it;              // 0..1023
            int row = idx >> 3, ch = idx & 7;
            uint32_t off = (uint32_t)(row * 128 + ch * 16);
            uint32_t swz = (off ^ ((off >> 3) & 0x70)) + (uint32_t)d * 16384u;
            CP_ASYNC16(aBase + swz,
                       g_att1h + (size_t)(n0 + row) * FC0V + kc * 64 + ch * 8);
            CP_ASYNC16(bBase + swz,
                       g_w2h + (size_t)(j0 + row) * FC0V + kc * 64 + ch * 8);
        }
    };

    stage(0, 0); CP_COMMIT();

    int lrow  = lane & 15;
    int lkoff = (lane >> 4) * 16;

    for (int kc = 0; kc < 4; ++kc) {
        if (kc < 3) { stage(kc + 1, (kc + 1) & 1); CP_COMMIT(); CP_WAIT1(); }
        else        { CP_WAIT0(); }
        __syncthreads();

        uint32_t dOff = (uint32_t)(kc & 1) * 16384u;
#pragma unroll
        for (int ks = 0; ks < 4; ++ks) {
            int kbyte = ks * 32 + lkoff;
            uint32_t a[4][4];
#pragma unroll
            for (int mf = 0; mf < 4; ++mf) {
                uint32_t off = (uint32_t)((warp_m + mf * 16 + lrow) * 128);
                uint32_t addr = aBase + dOff + ((off + kbyte) ^ ((off >> 3) & 0x70));
                LDMATRIX_X4(a[mf], addr);
            }
            uint32_t bm[2][4];
#pragma unroll
            for (int nf = 0; nf < 2; ++nf) {
                uint32_t off = (uint32_t)((warp_n + nf * 16 + lrow) * 128);
                uint32_t addr = bBase + dOff + ((off + kbyte) ^ ((off >> 3) & 0x70));
                LDMATRIX_X4(bm[nf], addr);
            }
#pragma unroll
            for (int mf = 0; mf < 4; ++mf)
#pragma unroll
                for (int n8 = 0; n8 < 4; ++n8)
                    MMA_16816(acc[mf][n8], a[mf],
                              bm[n8 >> 1][n8 & 1], bm[n8 >> 1][(n8 & 1) + 2]);
        }
        __syncthreads();
    }

    // epilogue: BN (log2-folded) + relu + exp2, store fp16
    int qrow = lane >> 2, qcol = (lane & 3) * 2;
#pragma unroll
    for (int mf = 0; mf < 4; ++mf) {
#pragma unroll
        for (int n8 = 0; n8 < 4; ++n8) {
            int cloc = warp_n + n8 * 8 + qcol;
            float sc0 = s_sc[cloc],   sc1 = s_sc[cloc + 1];
            float bi0 = s_bias[cloc], bi1 = s_bias[cloc + 1];
#pragma unroll
            for (int h = 0; h < 2; ++h) {
                int row = n0 + warp_m + mf * 16 + qrow + h * 8;
                float t0 = fmaf(acc[mf][n8][h * 2],     sc0, bi0);
                float t1 = fmaf(acc[mf][n8][h * 2 + 1], sc1, bi1);
                float e0 = t0 > 0.0f ? exp2f(t0) : 1.0f;
                float e1 = t1 > 0.0f ? exp2f(t1) : 1.0f;
                *(__half2*)(g_e + (size_t)row * KCH + j0 + cloc) =
                    __floats2half2_rn(e0, e1);
            }
        }
    }
}

// ---------------- pool via HMMA: poolsum[b] += e_b^T @ [x|1] -----------------
// grid = (64 row-chunks of 512, 8 k-tiles of 128ch). Warp w: 16 channels x 40.
__global__ void __launch_bounds__(256) pool_kernel()
{
    __shared__ __half e_s[64][136];   // padded: conflict-free trans-ldmatrix
    __shared__ __half x_s[64][40];

    int kt = blockIdx.y;
    int cs = blockIdx.x * 512;
    int ce = cs + 512;
    int tid = threadIdx.x, lane = tid & 31, wid = tid >> 5;

    uint32_t eBase = smem_u32(e_s), xBase = smem_u32(x_s);

    // A-fragment (e^T) lane address components: frag order (m,k) tiles
    int g = lane >> 3, l = lane & 7;
    int a_row = (g >> 1) * 8 + l;                    // + k0
    int a_col = wid * 16 + (g & 1) * 8;              // channel within tile
    // B-fragment (x, trans) lane address components
    int b_row = (g & 1) * 8 + l;                     // + k0
    int b_coff = (g >> 1) * 8;                       // + n0
    // x2-trans (n=32 col): lanes 0..15
    int b2_row = ((lane >> 3) & 1) * 8 + l;          // + k0

    int b = 0;
    while (g_offsets[b + 1] <= cs) ++b;

    float acc[5][4];
#pragma unroll
    for (int t = 0; t < 5; ++t)
#pragma unroll
        for (int q = 0; q < 4; ++q) acc[t][q] = 0.0f;

    int cur = cs;
    while (cur < ce) {
        int send = min(ce, g_offsets[b + 1]);

        for (int r0 = cur; r0 < send; r0 += 64) {
            int nr = min(64, send - r0);
            __syncthreads();
            // stage e tile (zero-fill beyond nr)
#pragma unroll
            for (int it = 0; it < 4; ++it) {
                int idx = tid + 256 * it;            // 0..1023
                int r = idx >> 4, c16 = idx & 15;
                uint4 v = make_uint4(0, 0, 0, 0);
                if (r < nr)
                    v = *(const uint4*)(g_e + (size_t)(r0 + r) * KCH + kt * 128 + c16 * 8);
                *(uint4*)((char*)e_s + r * 272 + c16 * 16) = v;
            }
            // stage x tile (zero-fill beyond nr)
#pragma unroll
            for (int it = 0; it < 2; ++it) {
                int idx = tid + 256 * it;            // need 320
                if (idx < 320) {
                    int r = idx / 5, c8 = idx % 5;
                    uint4 v = make_uint4(0, 0, 0, 0);
                    if (r < nr)
                        v = *(const uint4*)(g_xh + (size_t)(r0 + r) * 40 + c8 * 8);
                    *(uint4*)((char*)x_s + r * 80 + c8 * 16) = v;
                }
            }
            __syncthreads();

#pragma unroll
            for (int ks = 0; ks < 4; ++ks) {
                int k0 = ks * 16;
                uint32_t a[4];
                LDMATRIX_X4T(a, eBase + (uint32_t)((k0 + a_row) * 272 + a_col * 2));
                uint32_t b0[4], b1[4], b2[2];
                LDMATRIX_X4T(b0, xBase + (uint32_t)((k0 + b_row) * 80 + (b_coff) * 2));
                LDMATRIX_X4T(b1, xBase + (uint32_t)((k0 + b_row) * 80 + (16 + b_coff) * 2));
                LDMATRIX_X2T(b2, xBase + (uint32_t)((k0 + b2_row) * 80 + 32 * 2));
                MMA_16816(acc[0], a, b0[0], b0[1]);
                MMA_16816(acc[1], a, b0[2], b0[3]);
                MMA_16816(acc[2], a, b1[0], b1[1]);
                MMA_16816(acc[3], a, b1[2], b1[3]);
                MMA_16816(acc[4], a, b2[0], b2[1]);
            }
        }

        // flush segment b: c-frag (m16n8): rows lane>>2, +8; cols (lane&3)*2, +1
        int row0 = kt * 128 + wid * 16 + (lane >> 2);
        int col0 = (lane & 3) * 2;
        float* ps = g_poolsum + ((size_t)b * KCH) * 40;
#pragma unroll
        for (int t = 0; t < 5; ++t) {
            int c = t * 8 + col0;
            atomicAdd(&ps[(size_t)row0 * 40 + c],       acc[t][0]);
            atomicAdd(&ps[(size_t)row0 * 40 + c + 1],   acc[t][1]);
            atomicAdd(&ps[(size_t)(row0 + 8) * 40 + c],     acc[t][2]);
            atomicAdd(&ps[(size_t)(row0 + 8) * 40 + c + 1], acc[t][3]);
#pragma unroll
            for (int q = 0; q < 4; ++q) acc[t][q] = 0.0f;
        }
        ++b;
        cur = send;
    }
}

// ---------------- normalize: pooled[b,k,c] = ps[b,k,c] / (ps[b,k,32]*len) ----
__global__ void norm_kernel(const int* __restrict__ length) {
    int idx = blockIdx.x * 256 + threadIdx.x;     // 0 .. 524287
    int c = idx & 31, k = (idx >> 5) & 1023, b = idx >> 15;
    const float* ps = g_poolsum + ((size_t)b * KCH + k) * 40;
    g_pooled[idx] = ps[c] / (ps[32] * (float)length[b]);
}

// ---------------- FC: out_raw[b,j] += pooled[b,:] . fcw[j,:]  (split-K) ------
__global__ void __launch_bounds__(256) fc_kernel(const float* __restrict__ fcw)
{
    int warp = threadIdx.x >> 5, lane = threadIdx.x & 31;
    int j  = blockIdx.x * 8 + warp;
    int i0 = blockIdx.y * 2048;

    float acc[BSEG];
#pragma unroll
    for (int b = 0; b < BSEG; ++b) acc[b] = 0.0f;

    const float4* fw4 = (const float4*)(fcw + (size_t)j * (KCH * CIN) + i0);
#pragma unroll 4
    for (int it = 0; it < 16; ++it) {
        int i4 = it * 32 + lane;
        float4 f = fw4[i4];
#pragma unroll
        for (int b = 0; b < BSEG; ++b) {
            float4 p = ((const float4*)(g_pooled + (size_t)b * (KCH * CIN) + i0))[i4];
            acc[b] += f.x * p.x + f.y * p.y + f.z * p.z + f.w * p.w;
        }
    }
#pragma unroll
    for (int b = 0; b < BSEG; ++b) {
        float v = acc[b];
#pragma unroll
        for (int s = 16; s > 0; s >>= 1) v += __shfl_xor_sync(0xffffffffu, v, s);
        if (lane == 0) atomicAdd(&g_outraw[b * FC0V + j], v);
    }
}

// ---------------- final: BN3 + row L2-normalize -> d_out [16,256] ------------
__global__ void final_kernel(
    const float* __restrict__ fcb, const float* __restrict__ g3,
    const float* __restrict__ be3, const float* __restrict__ m3,
    const float* __restrict__ v3,  float* __restrict__ out)
{
    int b = blockIdx.x, j = threadIdx.x;
    float sc = g3[j] * rsqrtf(v3[j] + BN_EPS);
    float r  = fmaf(g_outraw[b * FC0V + j] + fcb[j] - m3[j], sc, be3[j]);

    __shared__ float red[256];
    red[j] = r * r;
    __syncthreads();
    for (int s = 128; s > 0; s >>= 1) {
        if (j < s) red[j] += red[j + s];
        __syncthreads();
    }
    float inv = 1.0f / fmaxf(sqrtf(red[0]), 1e-12f);
    out[b * FC0V + j] = r * inv;
}

// ---------------- launch -----------------------------------------------------
extern "C" void kernel_launch(void* const* d_in, const int* in_sizes, int n_in,
                              void* d_out, int out_size)
{
    const float* x      = (const float*)d_in[0];
    const int*   length = (const int*)  d_in[1];
    const float* w1  = (const float*)d_in[2];
    const float* b1  = (const float*)d_in[3];
    const float* g1  = (const float*)d_in[4];
    const float* be1 = (const float*)d_in[5];
    const float* m1  = (const float*)d_in[6];
    const float* v1  = (const float*)d_in[7];
    const float* w2  = (const float*)d_in[8];
    const float* b2  = (const float*)d_in[9];
    const float* g2  = (const float*)d_in[10];
    const float* be2 = (const float*)d_in[11];
    const float* m2  = (const float*)d_in[12];
    const float* v2  = (const float*)d_in[13];
    const float* fcw = (const float*)d_in[14];
    const float* fcb = (const float*)d_in[15];
    const float* g3  = (const float*)d_in[16];
    const float* be3 = (const float*)d_in[17];
    const float* m3  = (const float*)d_in[18];
    const float* v3  = (const float*)d_in[19];
    float* out = (float*)d_out;

    cudaFuncSetAttribute(gemm2_kernel,
                         cudaFuncAttributeMaxDynamicSharedMemorySize, 66560);

    prep_kernel<<<64, 256>>>(x, length, w2, b2, g2, be2, m2, v2);
    gemm1_kernel<<<NPTS / 64, 256>>>(x, w1, b1, g1, be1, m1, v1);
    gemm2_kernel<<<dim3(NPTS / 128, KCH / 128), 256, 66560>>>();
    pool_kernel<<<dim3(64, 8), 256>>>();
    norm_kernel<<<(BSEG * KCH * CIN) / 256, 256>>>(length);
    fc_kernel<<<dim3(FC0V / 8, 16), 256>>>(fcw);
    final_kernel<<<BSEG, 256>>>(fcb, g3, be3, m3, v3, out);
}

// round 5
// speedup vs baseline: 4.3464x; 1.0617x over previous
#include <cuda_runtime.h>
#include <cuda_fp16.h>
#include <math.h>
#include <stdint.h>

// Shapes (fixed by the problem)
#define NPTS  32768
#define CIN   32
#define FC0V  256
#define KCH   1024
#define BSEG  16
#define BN_EPS 1e-5f
#define LOG2E_F 1.44269504088896340736f

// ---------------- scratch (device globals; no allocations allowed) ----------
__device__ __half g_att1h[(size_t)NPTS * FC0V];        // 16 MB  fp16 att1
__device__ __half g_w2h[(size_t)KCH * FC0V];           // 512 KB fp16 w2
__device__ __half g_xh[(size_t)NPTS * 40];             // 2.6 MB fp16 [x | 1 | 0pad]
__device__ float  g_sc2[KCH];
__device__ float  g_bias2[KCH];
__device__ float  g_poolsum[(size_t)BSEG * KCH * 40];  // 2.6 MB (col 32 = esum)
__device__ float  g_pooled[(size_t)BSEG * KCH * CIN];  // 2 MB
__device__ float  g_outraw[BSEG * FC0V];
__device__ int    g_offsets[BSEG + 1];

// ---------------- helpers ----------------------------------------------------
__device__ __forceinline__ uint32_t smem_u32(const void* p) {
    uint32_t a;
    asm("{ .reg .u64 t; cvta.to.shared.u64 t, %1; cvt.u32.u64 %0, t; }"
        : "=r"(a) : "l"(p));
    return a;
}

#define LDMATRIX_X4(r, addr) \
    asm volatile("ldmatrix.sync.aligned.m8n8.x4.shared.b16 {%0,%1,%2,%3}, [%4];" \
        : "=r"((r)[0]), "=r"((r)[1]), "=r"((r)[2]), "=r"((r)[3]) : "r"(addr))

#define LDMATRIX_X4T(r, addr) \
    asm volatile("ldmatrix.sync.aligned.m8n8.x4.trans.shared.b16 {%0,%1,%2,%3}, [%4];" \
        : "=r"((r)[0]), "=r"((r)[1]), "=r"((r)[2]), "=r"((r)[3]) : "r"(addr))

#define LDMATRIX_X2T(r, addr) \
    asm volatile("ldmatrix.sync.aligned.m8n8.x2.trans.shared.b16 {%0,%1}, [%2];" \
        : "=r"((r)[0]), "=r"((r)[1]) : "r"(addr))

#define MMA_16816(d, a, b0, b1) \
    asm volatile("mma.sync.aligned.m16n8k16.row.col.f32.f16.f16.f32 " \
        "{%0,%1,%2,%3}, {%4,%5,%6,%7}, {%8,%9}, {%0,%1,%2,%3};" \
        : "+f"((d)[0]), "+f"((d)[1]), "+f"((d)[2]), "+f"((d)[3]) \
        : "r"((a)[0]), "r"((a)[1]), "r"((a)[2]), "r"((a)[3]), "r"(b0), "r"(b1))

#define CP_ASYNC16(dst, src) \
    asm volatile("cp.async.cg.shared.global [%0], [%1], 16;" :: "r"(dst), "l"(src))
#define CP_COMMIT() asm volatile("cp.async.commit_group;" ::: "memory")
#define CP_WAIT0()  asm volatile("cp.async.wait_group 0;" ::: "memory")

// ---------------- prep -------------------------------------------------------
__global__ void prep_kernel(const float* __restrict__ x,
                            const int* __restrict__ length, const float* __restrict__ w2,
                            const float* __restrict__ b2, const float* __restrict__ g2,
                            const float* __restrict__ be2, const float* __restrict__ m2,
                            const float* __restrict__ v2) {
    int gid = blockIdx.x * blockDim.x + threadIdx.x;
    int stride = gridDim.x * blockDim.x;
    for (int i = gid; i < BSEG * KCH * 40; i += stride) g_poolsum[i] = 0.0f;
    for (int i = gid; i < BSEG * FC0V; i += stride)     g_outraw[i] = 0.0f;
    for (int i = gid; i < KCH * FC0V; i += stride)      g_w2h[i] = __float2half(w2[i]);
    for (int n = gid; n < NPTS; n += stride) {
        __half* dst = g_xh + (size_t)n * 40;
#pragma unroll
        for (int c = 0; c < 32; ++c) dst[c] = __float2half(x[(size_t)n * CIN + c]);
        dst[32] = __float2half(1.0f);
#pragma unroll
        for (int c = 33; c < 40; ++c) dst[c] = __float2half(0.0f);
    }
    for (int j = gid; j < KCH; j += stride) {
        float sc = g2[j] * rsqrtf(v2[j] + BN_EPS);
        g_sc2[j]   = sc * LOG2E_F;
        g_bias2[j] = ((b2[j] - m2[j]) * sc + be2[j]) * LOG2E_F;
    }
    if (gid == 0) {
        int s = 0;
        for (int b = 0; b < BSEG; ++b) { g_offsets[b] = s; s += length[b]; }
        g_offsets[BSEG] = s;
    }
}

// ---------------- GEMM1: att1h = fp16(relu(bn1(x @ w1^T + b1))) --------------
__global__ void __launch_bounds__(256) gemm1_kernel(
    const float* __restrict__ x,  const float* __restrict__ w1,
    const float* __restrict__ b1, const float* __restrict__ g1,
    const float* __restrict__ be1,const float* __restrict__ m1,
    const float* __restrict__ v1)
{
    __shared__ float sx[64][33];
    int n0 = blockIdx.x * 64;
    int j  = threadIdx.x;

    float w[32];
    const float4* w4 = (const float4*)w1;
#pragma unroll
    for (int k2 = 0; k2 < 8; ++k2) {
        float4 v = w4[j * 8 + k2];
        w[4*k2+0] = v.x; w[4*k2+1] = v.y; w[4*k2+2] = v.z; w[4*k2+3] = v.w;
    }
#pragma unroll
    for (int it = 0; it < 8; ++it) {
        int idx = threadIdx.x + 256 * it;
        int r = idx >> 5, c = idx & 31;
        sx[r][c] = x[(size_t)(n0 + r) * CIN + c];
    }
    __syncthreads();

    float sc   = g1[j] * rsqrtf(v1[j] + BN_EPS);
    float bias = (b1[j] - m1[j]) * sc + be1[j];

    for (int r = 0; r < 64; ++r) {
        float dot = 0.0f;
#pragma unroll
        for (int k = 0; k < 32; ++k) dot = fmaf(sx[r][k], w[k], dot);
        float t = fmaf(dot, sc, bias);
        g_att1h[(size_t)(n0 + r) * FC0V + j] = __float2half(t > 0.0f ? t : 0.0f);
    }
}

// ---------------- fused GEMM2 + pool ------------------------------------------
// grid (37 row-chunks, 8 ch-tiles of 128). Per CTA: B tile resident; loop
// 32-row blocks: e = exp(relu(bn(A@B^T))) -> smem -> pool MMA e^T@[x|1],
// per-segment atomic flush into g_poolsum.
// dyn smem layout (110,592 B):
//   B tile   @ 0      (65536)   A bufs @ 65536 (2x16384)
//   e tile   @ 98304  (8704)    x tile @ 107008 (2560)
//   sc       @ 109568 (512)     bias   @ 110080 (512)
__global__ void __launch_bounds__(256, 2) fused2_kernel()
{
    extern __shared__ char dyn[];
    char*  Et     = dyn + 98304;
    char*  Xt     = dyn + 107008;
    float* s_sc   = (float*)(dyn + 109568);
    float* s_bias = (float*)(dyn + 110080);

    int tid = threadIdx.x, lane = tid & 31, wid = tid >> 5;
    int cid = blockIdx.x;            // 0..36
    int kt  = blockIdx.y;            // 0..7

    int blocks0 = cid * 27 + min(cid, 25);
    int nblk    = 27 + (cid < 25 ? 1 : 0);
    int cs      = blocks0 * 32;

    uint32_t bBase = smem_u32(dyn);
    uint32_t aBase = bBase + 65536u;
    uint32_t eBase = bBase + 98304u;
    uint32_t xBase = bBase + 107008u;

    // gemm2 warp tiling: 8 warps = 2m x 4n, warp tile 16 x 32
    int warp_m = (wid & 1) * 16;
    int warp_n = (wid >> 1) * 32;
    int lrow = lane & 15;
    int lhi  = (lane >> 4) * 16;
    int qrow = lane >> 2, qcol = (lane & 3) * 2;

    // pool fragment lane addressing (verified in round 4)
    int g = lane >> 3, l = lane & 7;
    int a_row  = (g >> 1) * 8 + l;
    int a_col  = wid * 16 + (g & 1) * 8;
    int b_row  = (g & 1) * 8 + l;
    int b_coff = (g >> 1) * 8;
    int b2_row = ((lane >> 3) & 1) * 8 + l;

    auto stageA = [&](int rowg, int buf) {
#pragma unroll
        for (int it = 0; it < 4; ++it) {
            int idx = tid + 256 * it;            // 0..1023
            int chunk = idx >> 8;
            int row = (idx >> 3) & 31;
            int c8 = idx & 7;
            uint32_t off = (uint32_t)(row * 128 + c8 * 16);
            CP_ASYNC16(aBase + (uint32_t)buf * 16384u + (uint32_t)chunk * 4096u
                           + (off ^ ((off >> 3) & 0x70)),
                       g_att1h + (size_t)(rowg + row) * FC0V + chunk * 64 + c8 * 8);
        }
    };
    auto stageX = [&](int rowg) {
        if (tid < 160) {
            int row = tid / 5, c8 = tid % 5;
            CP_ASYNC16(xBase + (uint32_t)(row * 80 + c8 * 16),
                       g_xh + (size_t)(rowg + row) * 40 + c8 * 8);
        }
    };
    auto poolmma = [&](float (*pc)[4]) {
#pragma unroll
        for (int ks = 0; ks < 2; ++ks) {
            int k0 = ks * 16;
            uint32_t a[4], b0[4], b1[4], b2[2];
            LDMATRIX_X4T(a,  eBase + (uint32_t)((k0 + a_row) * 272 + a_col * 2));
            LDMATRIX_X4T(b0, xBase + (uint32_t)((k0 + b_row) * 80 + b_coff * 2));
            LDMATRIX_X4T(b1, xBase + (uint32_t)((k0 + b_row) * 80 + (16 + b_coff) * 2));
            LDMATRIX_X2T(b2, xBase + (uint32_t)((k0 + b2_row) * 80 + 64));
            MMA_16816(pc[0], a, b0[0], b0[1]);
            MMA_16816(pc[1], a, b0[2], b0[3]);
            MMA_16816(pc[2], a, b1[0], b1[1]);
            MMA_16816(pc[3], a, b1[2], b1[3]);
            MMA_16816(pc[4], a, b2[0], b2[1]);
        }
    };
    auto flushp = [&](float (*pc)[4], int seg) {
        float* ps = g_poolsum + (size_t)seg * (KCH * 40);
        int row0 = kt * 128 + wid * 16 + (lane >> 2);
        int col0 = (lane & 3) * 2;
#pragma unroll
        for (int t = 0; t < 5; ++t) {
            int c = t * 8 + col0;
            atomicAdd(&ps[(size_t)row0 * 40 + c],           pc[t][0]);
            atomicAdd(&ps[(size_t)row0 * 40 + c + 1],       pc[t][1]);
            atomicAdd(&ps[(size_t)(row0 + 8) * 40 + c],     pc[t][2]);
            atomicAdd(&ps[(size_t)(row0 + 8) * 40 + c + 1], pc[t][3]);
#pragma unroll
            for (int q = 0; q < 4; ++q) pc[t][q] = 0.0f;
        }
    };
    auto zeroX = [&](int ra, int rb) {
        if (tid < 160) {
            int row = tid / 5, c8 = tid % 5;
            if (row >= ra && row < rb)
                *(uint4*)(Xt + row * 80 + c8 * 16) = make_uint4(0, 0, 0, 0);
        }
    };
    auto loadX = [&](int rowg, int ra, int rb) {
        if (tid < 160) {
            int row = tid / 5, c8 = tid % 5;
            if (row >= ra && row < rb)
                *(uint4*)(Xt + row * 80 + c8 * 16) =
                    *(const uint4*)(g_xh + (size_t)(rowg + row) * 40 + c8 * 8);
        }
    };

    // bootstrap: B tile + first A block + first x block + epilogue params
#pragma unroll
    for (int it = 0; it < 16; ++it) {
        int idx = tid + 256 * it;                // 0..4095
        int chunk = idx >> 10;
        int row = (idx >> 3) & 127;
        int c8 = idx & 7;
        uint32_t off = (uint32_t)(row * 128 + c8 * 16);
        CP_ASYNC16(bBase + (uint32_t)chunk * 16384u + (off ^ ((off >> 3) & 0x70)),
                   g_w2h + (size_t)(kt * 128 + row) * FC0V + chunk * 64 + c8 * 8);
    }
    stageA(cs, 0);
    stageX(cs);
    if (tid < 128) {
        s_sc[tid]   = g_sc2[kt * 128 + tid];
        s_bias[tid] = g_bias2[kt * 128 + tid];
    }
    CP_COMMIT();
    CP_WAIT0();
    __syncthreads();

    int b = 0;
    while (g_offsets[b + 1] <= cs) ++b;

    float pacc[5][4];
#pragma unroll
    for (int t = 0; t < 5; ++t)
#pragma unroll
        for (int q = 0; q < 4; ++q) pacc[t][q] = 0.0f;

    int p = 0;
    for (int blk = 0; blk < nblk; ++blk) {
        int r0 = cs + blk * 32;
        if (blk + 1 < nblk) stageA(r0 + 32, p ^ 1);
        CP_COMMIT();

        // gemm2: 32 rows x 128 ch, K=256
        float acc[4][4];
#pragma unroll
        for (int n8 = 0; n8 < 4; ++n8)
#pragma unroll
            for (int q = 0; q < 4; ++q) acc[n8][q] = 0.0f;

        uint32_t aB = aBase + (uint32_t)p * 16384u;
#pragma unroll
        for (int ks = 0; ks < 16; ++ks) {
            int chunk = ks >> 2;
            int kbyte = (ks & 3) * 32 + lhi;
            uint32_t a[4], bm[2][4];
            {
                uint32_t off = (uint32_t)((warp_m + lrow) * 128);
                LDMATRIX_X4(a, aB + (uint32_t)chunk * 4096u
                                 + ((off + kbyte) ^ ((off >> 3) & 0x70)));
            }
#pragma unroll
            for (int nf = 0; nf < 2; ++nf) {
                uint32_t off = (uint32_t)((warp_n + nf * 16 + lrow) * 128);
                LDMATRIX_X4(bm[nf], bBase + (uint32_t)chunk * 16384u
                                       + ((off + kbyte) ^ ((off >> 3) & 0x70)));
            }
#pragma unroll
            for (int n8 = 0; n8 < 4; ++n8)
                MMA_16816(acc[n8], a, bm[n8 >> 1][n8 & 1], bm[n8 >> 1][(n8 & 1) + 2]);
        }

        // epilogue: BN(log2) + relu + exp2 -> e smem tile
#pragma unroll
        for (int n8 = 0; n8 < 4; ++n8) {
            int col = warp_n + n8 * 8 + qcol;
            float sc0 = s_sc[col],   sc1 = s_sc[col + 1];
            float bi0 = s_bias[col], bi1 = s_bias[col + 1];
#pragma unroll
            for (int h = 0; h < 2; ++h) {
                int row = warp_m + qrow + h * 8;
                float t0 = fmaf(acc[n8][h * 2],     sc0, bi0);
                float t1 = fmaf(acc[n8][h * 2 + 1], sc1, bi1);
                float e0 = t0 > 0.0f ? exp2f(t0) : 1.0f;
                float e1 = t1 > 0.0f ? exp2f(t1) : 1.0f;
                *(__half2*)(Et + row * 272 + col * 2) = __floats2half2_rn(e0, e1);
            }
        }
        __syncthreads();

        // pool this block, handling at most one segment boundary inside
        int send = g_offsets[b + 1];
        if (send >= r0 + 32) {
            poolmma(pacc);
            if (send == r0 + 32) { flushp(pacc, b); ++b; }
        } else {
            int rb = send - r0;                  // 1..31
            zeroX(rb, 32);
            __syncthreads();
            poolmma(pacc);
            flushp(pacc, b); ++b;
            __syncthreads();
            loadX(r0, rb, 32);
            zeroX(0, rb);
            __syncthreads();
            poolmma(pacc);
        }
        __syncthreads();

        if (blk + 1 < nblk) stageX(r0 + 32);
        CP_COMMIT();
        CP_WAIT0();
        __syncthreads();
        p ^= 1;
    }
    flushp(pacc, min(b, BSEG - 1));
}

// ---------------- normalize: pooled[b,k,c] = ps[b,k,c] / (ps[b,k,32]*len) ----
__global__ void norm_kernel(const int* __restrict__ length) {
    int idx = blockIdx.x * 256 + threadIdx.x;     // 0 .. 524287
    int c = idx & 31, k = (idx >> 5) & 1023, b = idx >> 15;
    const float* ps = g_poolsum + ((size_t)b * KCH + k) * 40;
    g_pooled[idx] = ps[c] / (ps[32] * (float)length[b]);
}

// ---------------- FC: out_raw[b,j] += pooled[b,:] . fcw[j,:]  (split-K) ------
__global__ void __launch_bounds__(256) fc_kernel(const float* __restrict__ fcw)
{
    int warp = threadIdx.x >> 5, lane = threadIdx.x & 31;
    int j  = blockIdx.x * 8 + warp;
    int i0 = blockIdx.y * 2048;

    float acc[BSEG];
#pragma unroll
    for (int b = 0; b < BSEG; ++b) acc[b] = 0.0f;

    const float4* fw4 = (const float4*)(fcw + (size_t)j * (KCH * CIN) + i0);
#pragma unroll 4
    for (int it = 0; it < 16; ++it) {
        int i4 = it * 32 + lane;
        float4 f = fw4[i4];
#pragma unroll
        for (int b = 0; b < BSEG; ++b) {
            float4 p = ((const float4*)(g_pooled + (size_t)b * (KCH * CIN) + i0))[i4];
            acc[b] += f.x * p.x + f.y * p.y + f.z * p.z + f.w * p.w;
        }
    }
#pragma unroll
    for (int b = 0; b < BSEG; ++b) {
        float v = acc[b];
#pragma unroll
        for (int s = 16; s > 0; s >>= 1) v += __shfl_xor_sync(0xffffffffu, v, s);
        if (lane == 0) atomicAdd(&g_outraw[b * FC0V + j], v);
    }
}

// ---------------- final: BN3 + row L2-normalize -> d_out [16,256] ------------
__global__ void final_kernel(
    const float* __restrict__ fcb, const float* __restrict__ g3,
    const float* __restrict__ be3, const float* __restrict__ m3,
    const float* __restrict__ v3,  float* __restrict__ out)
{
    int b = blockIdx.x, j = threadIdx.x;
    float sc = g3[j] * rsqrtf(v3[j] + BN_EPS);
    float r  = fmaf(g_outraw[b * FC0V + j] + fcb[j] - m3[j], sc, be3[j]);

    __shared__ float red[256];
    red[j] = r * r;
    __syncthreads();
    for (int s = 128; s > 0; s >>= 1) {
        if (j < s) red[j] += red[j + s];
        __syncthreads();
    }
    float inv = 1.0f / fmaxf(sqrtf(red[0]), 1e-12f);
    out[b * FC0V + j] = r * inv;
}

// ---------------- launch -----------------------------------------------------
extern "C" void kernel_launch(void* const* d_in, const int* in_sizes, int n_in,
                              void* d_out, int out_size)
{
    const float* x      = (const float*)d_in[0];
    const int*   length = (const int*)  d_in[1];
    const float* w1  = (const float*)d_in[2];
    const float* b1  = (const float*)d_in[3];
    const float* g1  = (const float*)d_in[4];
    const float* be1 = (const float*)d_in[5];
    const float* m1  = (const float*)d_in[6];
    const float* v1  = (const float*)d_in[7];
    const float* w2  = (const float*)d_in[8];
    const float* b2  = (const float*)d_in[9];
    const float* g2  = (const float*)d_in[10];
    const float* be2 = (const float*)d_in[11];
    const float* m2  = (const float*)d_in[12];
    const float* v2  = (const float*)d_in[13];
    const float* fcw = (const float*)d_in[14];
    const float* fcb = (const float*)d_in[15];
    const float* g3  = (const float*)d_in[16];
    const float* be3 = (const float*)d_in[17];
    const float* m3  = (const float*)d_in[18];
    const float* v3  = (const float*)d_in[19];
    float* out = (float*)d_out;

    cudaFuncSetAttribute(fused2_kernel,
                         cudaFuncAttributeMaxDynamicSharedMemorySize, 110592);

    prep_kernel<<<64, 256>>>(x, length, w2, b2, g2, be2, m2, v2);
    gemm1_kernel<<<NPTS / 64, 256>>>(x, w1, b1, g1, be1, m1, v1);
    fused2_kernel<<<dim3(37, 8), 256, 110592>>>();
    norm_kernel<<<(BSEG * KCH * CIN) / 256, 256>>>(length);
    fc_kernel<<<dim3(FC0V / 8, 16), 256>>>(fcw);
    final_kernel<<<BSEG, 256>>>(fcb, g3, be3, m3, v3, out);
}

// round 6
// speedup vs baseline: 5.0794x; 1.1686x over previous
#include <cuda_runtime.h>
#include <cuda_fp16.h>
#include <math.h>
#include <stdint.h>

// Shapes (fixed by the problem)
#define NPTS  32768
#define CIN   32
#define FC0V  256
#define KCH   1024
#define BSEG  16
#define BN_EPS 1e-5f
#define LOG2E_F 1.44269504088896340736f

// ---------------- scratch (device globals; no allocations allowed) ----------
__device__ __half g_att1h[(size_t)NPTS * FC0V];        // 16 MB  fp16 att1
__device__ __half g_w2h[(size_t)KCH * FC0V];           // 512 KB fp16 w2
__device__ __half g_w1h[FC0V * CIN];                   // 16 KB  fp16 w1
__device__ __half g_xh[(size_t)NPTS * 40];             // 2.6 MB fp16 [x | 1 | 0pad]
__device__ float  g_sc1[FC0V], g_bias1[FC0V];
__device__ float  g_sc2[KCH],  g_bias2[KCH];
__device__ float  g_poolsum[(size_t)BSEG * KCH * 40];  // 2.6 MB (col 32 = esum)
__device__ float  g_pooled[(size_t)BSEG * KCH * CIN];  // 2 MB
__device__ float  g_outraw[BSEG * FC0V];
__device__ int    g_offsets[BSEG + 1];

// ---------------- helpers ----------------------------------------------------
__device__ __forceinline__ uint32_t smem_u32(const void* p) {
    uint32_t a;
    asm("{ .reg .u64 t; cvta.to.shared.u64 t, %1; cvt.u32.u64 %0, t; }"
        : "=r"(a) : "l"(p));
    return a;
}

#define LDMATRIX_X4(r, addr) \
    asm volatile("ldmatrix.sync.aligned.m8n8.x4.shared.b16 {%0,%1,%2,%3}, [%4];" \
        : "=r"((r)[0]), "=r"((r)[1]), "=r"((r)[2]), "=r"((r)[3]) : "r"(addr))

#define LDMATRIX_X4T(r, addr) \
    asm volatile("ldmatrix.sync.aligned.m8n8.x4.trans.shared.b16 {%0,%1,%2,%3}, [%4];" \
        : "=r"((r)[0]), "=r"((r)[1]), "=r"((r)[2]), "=r"((r)[3]) : "r"(addr))

#define LDMATRIX_X2T(r, addr) \
    asm volatile("ldmatrix.sync.aligned.m8n8.x2.trans.shared.b16 {%0,%1}, [%2];" \
        : "=r"((r)[0]), "=r"((r)[1]) : "r"(addr))

#define MMA_16816(d, a, b0, b1) \
    asm volatile("mma.sync.aligned.m16n8k16.row.col.f32.f16.f16.f32 " \
        "{%0,%1,%2,%3}, {%4,%5,%6,%7}, {%8,%9}, {%0,%1,%2,%3};" \
        : "+f"((d)[0]), "+f"((d)[1]), "+f"((d)[2]), "+f"((d)[3]) \
        : "r"((a)[0]), "r"((a)[1]), "r"((a)[2]), "r"((a)[3]), "r"(b0), "r"(b1))

#define CP_ASYNC16(dst, src) \
    asm volatile("cp.async.cg.shared.global [%0], [%1], 16;" :: "r"(dst), "l"(src))
#define CP_COMMIT() asm volatile("cp.async.commit_group;" ::: "memory")
#define CP_WAIT1()  asm volatile("cp.async.wait_group 1;" ::: "memory")
#define CP_WAIT0()  asm volatile("cp.async.wait_group 0;" ::: "memory")

// ---------------- prep -------------------------------------------------------
__global__ void prep_kernel(const float* __restrict__ x,
                            const int* __restrict__ length,
                            const float* __restrict__ w1, const float* __restrict__ b1,
                            const float* __restrict__ g1, const float* __restrict__ be1,
                            const float* __restrict__ m1, const float* __restrict__ v1,
                            const float* __restrict__ w2, const float* __restrict__ b2,
                            const float* __restrict__ g2, const float* __restrict__ be2,
                            const float* __restrict__ m2, const float* __restrict__ v2) {
    int gid = blockIdx.x * blockDim.x + threadIdx.x;
    int stride = gridDim.x * blockDim.x;
    for (int i = gid; i < BSEG * KCH * 40; i += stride) g_poolsum[i] = 0.0f;
    for (int i = gid; i < BSEG * FC0V; i += stride)     g_outraw[i] = 0.0f;
    for (int i = gid; i < KCH * FC0V; i += stride)      g_w2h[i] = __float2half(w2[i]);
    for (int i = gid; i < FC0V * CIN; i += stride)      g_w1h[i] = __float2half(w1[i]);
    for (int n = gid; n < NPTS; n += stride) {
        __half* dst = g_xh + (size_t)n * 40;
#pragma unroll
        for (int c = 0; c < 32; ++c) dst[c] = __float2half(x[(size_t)n * CIN + c]);
        dst[32] = __float2half(1.0f);
#pragma unroll
        for (int c = 33; c < 40; ++c) dst[c] = __float2half(0.0f);
    }
    for (int j = gid; j < FC0V; j += stride) {
        float sc = g1[j] * rsqrtf(v1[j] + BN_EPS);
        g_sc1[j]   = sc;
        g_bias1[j] = (b1[j] - m1[j]) * sc + be1[j];
    }
    for (int j = gid; j < KCH; j += stride) {
        float sc = g2[j] * rsqrtf(v2[j] + BN_EPS);
        g_sc2[j]   = sc * LOG2E_F;
        g_bias2[j] = ((b2[j] - m2[j]) * sc + be2[j]) * LOG2E_F;
    }
    if (gid == 0) {
        int s = 0;
        for (int b = 0; b < BSEG; ++b) { g_offsets[b] = s; s += length[b]; }
        g_offsets[BSEG] = s;
    }
}

// ---------------- GEMM1 (HMMA): att1h = fp16(relu(bn1(x @ w1^T + b1))) -------
// grid 256, 512 thr. CTA: 128 rows x 256 out. 16 warps = 4m x 4n, warp 32x64.
__global__ void __launch_bounds__(512) gemm1_kernel()
{
    __shared__ __half xs[128 * 40];   // stride 80 B (conflict-free ldmatrix)
    __shared__ __half ws[256 * 40];
    __shared__ float  ssc[256], sbia[256];

    int tid = threadIdx.x, lane = tid & 31, wid = tid >> 5;
    int n0 = blockIdx.x * 128;
    uint32_t xsB = smem_u32(xs), wsB = smem_u32(ws);

    {   // stage x rows (512 jobs)
        int row = tid >> 2, c = tid & 3;
        CP_ASYNC16(xsB + (uint32_t)(row * 80 + c * 16),
                   g_xh + (size_t)(n0 + row) * 40 + c * 8);
    }
#pragma unroll
    for (int it = 0; it < 2; ++it) {   // stage w1 (1024 jobs)
        int idx = tid + 512 * it;
        int row = idx >> 2, c = idx & 3;
        CP_ASYNC16(wsB + (uint32_t)(row * 80 + c * 16), g_w1h + row * 32 + c * 8);
    }
    if (tid < 256) { ssc[tid] = g_sc1[tid]; sbia[tid] = g_bias1[tid]; }
    CP_COMMIT(); CP_WAIT0(); __syncthreads();

    int warp_m = (wid & 3) * 32, warp_n = (wid >> 2) * 64;
    int lrow = lane & 15, lhi = (lane >> 4) * 16;

    float acc[2][8][4];
#pragma unroll
    for (int mf = 0; mf < 2; ++mf)
#pragma unroll
        for (int n8 = 0; n8 < 8; ++n8)
#pragma unroll
            for (int q = 0; q < 4; ++q) acc[mf][n8][q] = 0.0f;

#pragma unroll
    for (int ks = 0; ks < 2; ++ks) {
        int kbyte = ks * 32 + lhi;
        uint32_t a[2][4], bm[4][4];
#pragma unroll
        for (int mf = 0; mf < 2; ++mf)
            LDMATRIX_X4(a[mf], xsB + (uint32_t)((warp_m + mf * 16 + lrow) * 80 + kbyte));
#pragma unroll
        for (int nf = 0; nf < 4; ++nf)
            LDMATRIX_X4(bm[nf], wsB + (uint32_t)((warp_n + nf * 16 + lrow) * 80 + kbyte));
#pragma unroll
        for (int mf = 0; mf < 2; ++mf)
#pragma unroll
            for (int n8 = 0; n8 < 8; ++n8)
                MMA_16816(acc[mf][n8], a[mf],
                          bm[n8 >> 1][n8 & 1], bm[n8 >> 1][(n8 & 1) + 2]);
    }

    int qrow = lane >> 2, qcol = (lane & 3) * 2;
#pragma unroll
    for (int mf = 0; mf < 2; ++mf)
#pragma unroll
        for (int n8 = 0; n8 < 8; ++n8) {
            int col = warp_n + n8 * 8 + qcol;
            float sc0 = ssc[col], sc1 = ssc[col + 1];
            float bi0 = sbia[col], bi1 = sbia[col + 1];
#pragma unroll
            for (int hh = 0; hh < 2; ++hh) {
                int row = n0 + warp_m + mf * 16 + qrow + hh * 8;
                float t0 = fmaf(acc[mf][n8][hh * 2],     sc0, bi0);
                float t1 = fmaf(acc[mf][n8][hh * 2 + 1], sc1, bi1);
                *(__half2*)(g_att1h + (size_t)row * FC0V + col) =
                    __floats2half2_rn(t0 > 0.f ? t0 : 0.f, t1 > 0.f ? t1 : 0.f);
            }
        }
}

// ---------------- fused GEMM2 + pool (512 thr, 1 CTA/SM) ---------------------
// grid (18, 8). CTA tile 128 rows x 128 ch, K=256 in 2 halves (A double-buf).
// dyn smem (187,392 B): B@0 (64K) | A@65536 (2x32K) | Et@131072 (34816)
//                       | Xt@165888 (2x10240) | sc@186368 | bias@186880
__global__ void __launch_bounds__(512, 1) fused2_kernel()
{
    extern __shared__ char dyn[];
    float* s_sc = (float*)(dyn + 186368);
    float* s_bi = (float*)(dyn + 186880);

    int tid = threadIdx.x, lane = tid & 31, wid = tid >> 5;
    int cid = blockIdx.x, kt = blockIdx.y;

    int blocks0 = cid * 14 + min(cid, 4);
    int nblk    = 14 + (cid < 4 ? 1 : 0);
    int cs      = blocks0 * 128;

    uint32_t bBase = smem_u32(dyn);
    uint32_t aBase = bBase + 65536u;
    uint32_t eBase = bBase + 131072u;
    uint32_t xBase = bBase + 165888u;

    // gemm2 tiling: 16 warps = 4m x 4n, warp tile 32x32
    int warp_m = (wid & 3) * 32, warp_n = (wid >> 2) * 32;
    int lrow = lane & 15, lhi = (lane >> 4) * 16;
    int qrow = lane >> 2, qcol = (lane & 3) * 2;

    // pool lane addressing: warps split rows (wgk) x channels (wch)
    int g = lane >> 3, l = lane & 7;
    int wgk = wid >> 3;                 // 0: rows 0-63, 1: rows 64-127
    int wch = wid & 7;                  // 16-channel tile
    int a_colp = wch * 16 + (g & 1) * 8;
    int a_rowp = (g >> 1) * 8 + l;
    int b_rowp = (g & 1) * 8 + l;
    int b_coff = (g >> 1) * 8;
    int b2_rowp = ((lane >> 3) & 1) * 8 + l;

    auto stageA = [&](int rowg, int h, int buf) {
#pragma unroll
        for (int it = 0; it < 4; ++it) {
            int idx = tid + 512 * it;            // 0..2047
            int chunk = idx >> 10;
            int row = (idx >> 3) & 127;
            int c8 = idx & 7;
            uint32_t off = (uint32_t)(row * 128 + c8 * 16);
            CP_ASYNC16(aBase + (uint32_t)buf * 32768u + (uint32_t)chunk * 16384u
                           + (off ^ ((off >> 3) & 0x70)),
                       g_att1h + (size_t)(rowg + row) * FC0V + h * 128 + chunk * 64 + c8 * 8);
        }
    };
    auto stageX = [&](int rowg, int buf) {
#pragma unroll
        for (int it = 0; it < 2; ++it) {
            int idx = tid + 512 * it;
            if (idx < 640) {
                int row = idx / 5, c8 = idx % 5;
                CP_ASYNC16(xBase + (uint32_t)buf * 10240u + (uint32_t)(row * 80 + c8 * 16),
                           g_xh + (size_t)(rowg + row) * 40 + c8 * 8);
            }
        }
    };
    auto gemm2half = [&](int h, int abuf, float (*acc)[4][4]) {
#pragma unroll
        for (int ks = 0; ks < 8; ++ks) {
            int chunk = ks >> 2;
            int kbyte = (ks & 3) * 32 + lhi;
            uint32_t a[2][4], bm[2][4];
#pragma unroll
            for (int mf = 0; mf < 2; ++mf) {
                uint32_t off = (uint32_t)((warp_m + mf * 16 + lrow) * 128);
                LDMATRIX_X4(a[mf], aBase + (uint32_t)abuf * 32768u
                                 + (uint32_t)chunk * 16384u
                                 + ((off + kbyte) ^ ((off >> 3) & 0x70)));
            }
#pragma unroll
            for (int nf = 0; nf < 2; ++nf) {
                uint32_t off = (uint32_t)((warp_n + nf * 16 + lrow) * 128);
                LDMATRIX_X4(bm[nf], bBase + (uint32_t)(h * 2 + chunk) * 16384u
                                  + ((off + kbyte) ^ ((off >> 3) & 0x70)));
            }
#pragma unroll
            for (int mf = 0; mf < 2; ++mf)
#pragma unroll
                for (int n8 = 0; n8 < 4; ++n8)
                    MMA_16816(acc[mf][n8], a[mf],
                              bm[n8 >> 1][n8 & 1], bm[n8 >> 1][(n8 & 1) + 2]);
        }
    };
    auto epilogue = [&](float (*acc)[4][4]) {
#pragma unroll
        for (int mf = 0; mf < 2; ++mf)
#pragma unroll
            for (int n8 = 0; n8 < 4; ++n8) {
                int col = warp_n + n8 * 8 + qcol;
                float sc0 = s_sc[col], sc1 = s_sc[col + 1];
                float bi0 = s_bi[col], bi1 = s_bi[col + 1];
#pragma unroll
                for (int hh = 0; hh < 2; ++hh) {
                    int row = warp_m + mf * 16 + qrow + hh * 8;
                    float t0 = fmaf(acc[mf][n8][hh * 2],     sc0, bi0);
                    float t1 = fmaf(acc[mf][n8][hh * 2 + 1], sc1, bi1);
                    float e0 = t0 > 0.0f ? exp2f(t0) : 1.0f;
                    float e1 = t1 > 0.0f ? exp2f(t1) : 1.0f;
                    *(__half2*)(dyn + 131072 + row * 272 + col * 2) =
                        __floats2half2_rn(e0, e1);
                }
            }
    };
    auto poolmma = [&](float (*pc)[4], int xbuf) {
        uint32_t xb = xBase + (uint32_t)xbuf * 10240u;
#pragma unroll
        for (int ks = 0; ks < 4; ++ks) {
            int k0 = wgk * 64 + ks * 16;
            uint32_t a[4], b0[4], b1[4], b2[2];
            LDMATRIX_X4T(a,  eBase + (uint32_t)((k0 + a_rowp) * 272 + a_colp * 2));
            LDMATRIX_X4T(b0, xb + (uint32_t)((k0 + b_rowp) * 80 + b_coff * 2));
            LDMATRIX_X4T(b1, xb + (uint32_t)((k0 + b_rowp) * 80 + (16 + b_coff) * 2));
            LDMATRIX_X2T(b2, xb + (uint32_t)((k0 + b2_rowp) * 80 + 64));
            MMA_16816(pc[0], a, b0[0], b0[1]);
            MMA_16816(pc[1], a, b0[2], b0[3]);
            MMA_16816(pc[2], a, b1[0], b1[1]);
            MMA_16816(pc[3], a, b1[2], b1[3]);
            MMA_16816(pc[4], a, b2[0], b2[1]);
        }
    };
    auto flushp = [&](float (*pc)[4], int seg) {
        float* ps = g_poolsum + (size_t)seg * (KCH * 40);
        int row0 = kt * 128 + wch * 16 + (lane >> 2);
        int col0 = (lane & 3) * 2;
#pragma unroll
        for (int t = 0; t < 5; ++t) {
            int c = t * 8 + col0;
            atomicAdd(&ps[(size_t)row0 * 40 + c],           pc[t][0]);
            atomicAdd(&ps[(size_t)row0 * 40 + c + 1],       pc[t][1]);
            atomicAdd(&ps[(size_t)(row0 + 8) * 40 + c],     pc[t][2]);
            atomicAdd(&ps[(size_t)(row0 + 8) * 40 + c + 1], pc[t][3]);
#pragma unroll
            for (int q = 0; q < 4; ++q) pc[t][q] = 0.0f;
        }
    };
    auto maskX = [&](int rowg, int xbuf, int ra, int rb, bool load) {
#pragma unroll
        for (int it = 0; it < 2; ++it) {
            int idx = tid + 512 * it;
            if (idx < 640) {
                int row = idx / 5, c8 = idx % 5;
                if (row >= ra && row < rb) {
                    uint4 v = make_uint4(0, 0, 0, 0);
                    if (load)
                        v = *(const uint4*)(g_xh + (size_t)(rowg + row) * 40 + c8 * 8);
                    *(uint4*)(dyn + 165888 + xbuf * 10240 + row * 80 + c8 * 16) = v;
                }
            }
        }
    };

    // prologue: B tile + A(0,h0) + X(0) [group 0]; A(0,h1) [group 1]
#pragma unroll
    for (int it = 0; it < 8; ++it) {
        int idx = tid + 512 * it;                // 0..4095
        int chunk = idx >> 10;
        int row = (idx >> 3) & 127;
        int c8 = idx & 7;
        uint32_t off = (uint32_t)(row * 128 + c8 * 16);
        CP_ASYNC16(bBase + (uint32_t)chunk * 16384u + (off ^ ((off >> 3) & 0x70)),
                   g_w2h + (size_t)(kt * 128 + row) * FC0V + chunk * 64 + c8 * 8);
    }
    stageA(cs, 0, 0);
    stageX(cs, 0);
    if (tid < 128) {
        s_sc[tid] = g_sc2[kt * 128 + tid];
        s_bi[tid] = g_bias2[kt * 128 + tid];
    }
    CP_COMMIT();
    stageA(cs, 1, 1);
    CP_COMMIT();

    int b = 0;
    while (g_offsets[b + 1] <= cs) ++b;

    float pacc[5][4];
#pragma unroll
    for (int t = 0; t < 5; ++t)
#pragma unroll
        for (int q = 0; q < 4; ++q) pacc[t][q] = 0.0f;

    for (int blk = 0; blk < nblk; ++blk) {
        int r0 = cs + blk * 128;
        bool more = (blk + 1 < nblk);

        CP_WAIT1();                 // A(blk,h0) (+X(blk)/B on blk 0) ready
        __syncthreads();

        float acc[2][4][4];
#pragma unroll
        for (int mf = 0; mf < 2; ++mf)
#pragma unroll
            for (int n8 = 0; n8 < 4; ++n8)
#pragma unroll
                for (int q = 0; q < 4; ++q) acc[mf][n8][q] = 0.0f;

        gemm2half(0, 0, acc);
        __syncthreads();            // abuf0 reads done
        if (more) stageA(r0 + 128, 0, 0);
        CP_COMMIT();
        CP_WAIT1();                 // A(blk,h1) ready
        __syncthreads();

        gemm2half(1, 1, acc);
        epilogue(acc);
        __syncthreads();            // Et ready; abuf1 reads done
        if (more) { stageA(r0 + 128, 1, 1); stageX(r0 + 128, (blk + 1) & 1); }
        CP_COMMIT();

        // pool this block (at most one segment boundary inside)
        int send = g_offsets[b + 1];
        int xb = blk & 1;
        if (send >= r0 + 128) {
            poolmma(pacc, xb);
            if (send == r0 + 128) { flushp(pacc, b); ++b; }
        } else {
            int rb = send - r0;                  // 1..127
            maskX(r0, xb, rb, 128, false);
            __syncthreads();
            poolmma(pacc, xb);
            flushp(pacc, b); ++b;
            __syncthreads();
            maskX(r0, xb, rb, 128, true);
            maskX(r0, xb, 0, rb, false);
            __syncthreads();
            poolmma(pacc, xb);
        }
        __syncthreads();            // Et/Xt reuse safe
    }
    flushp(pacc, min(b, BSEG - 1));
}

// ---------------- normalize: pooled[b,k,c] = ps[b,k,c] / (ps[b,k,32]*len) ----
__global__ void norm_kernel(const int* __restrict__ length) {
    int idx = blockIdx.x * 256 + threadIdx.x;     // 0 .. 524287
    int c = idx & 31, k = (idx >> 5) & 1023, b = idx >> 15;
    const float* ps = g_poolsum + ((size_t)b * KCH + k) * 40;
    g_pooled[idx] = ps[c] / (ps[32] * (float)length[b]);
}

// ---------------- FC: out_raw[b,j] += pooled[b,:] . fcw[j,:]  (split-K) ------
__global__ void __launch_bounds__(256) fc_kernel(const float* __restrict__ fcw)
{
    int warp = threadIdx.x >> 5, lane = threadIdx.x & 31;
    int j  = blockIdx.x * 8 + warp;
    int i0 = blockIdx.y * 2048;

    float acc[BSEG];
#pragma unroll
    for (int b = 0; b < BSEG; ++b) acc[b] = 0.0f;

    const float4* fw4 = (const float4*)(fcw + (size_t)j * (KCH * CIN) + i0);
#pragma unroll 4
    for (int it = 0; it < 16; ++it) {
        int i4 = it * 32 + lane;
        float4 f = fw4[i4];
#pragma unroll
        for (int b = 0; b < BSEG; ++b) {
            float4 p = ((const float4*)(g_pooled + (size_t)b * (KCH * CIN) + i0))[i4];
            acc[b] += f.x * p.x + f.y * p.y + f.z * p.z + f.w * p.w;
        }
    }
#pragma unroll
    for (int b = 0; b < BSEG; ++b) {
        float v = acc[b];
#pragma unroll
        for (int s = 16; s > 0; s >>= 1) v += __shfl_xor_sync(0xffffffffu, v, s);
        if (lane == 0) atomicAdd(&g_outraw[b * FC0V + j], v);
    }
}

// ---------------- final: BN3 + row L2-normalize -> d_out [16,256] ------------
__global__ void final_kernel(
    const float* __restrict__ fcb, const float* __restrict__ g3,
    const float* __restrict__ be3, const float* __restrict__ m3,
    const float* __restrict__ v3,  float* __restrict__ out)
{
    int b = blockIdx.x, j = threadIdx.x;
    float sc = g3[j] * rsqrtf(v3[j] + BN_EPS);
    float r  = fmaf(g_outraw[b * FC0V + j] + fcb[j] - m3[j], sc, be3[j]);

    __shared__ float red[256];
    red[j] = r * r;
    __syncthreads();
    for (int s = 128; s > 0; s >>= 1) {
        if (j < s) red[j] += red[j + s];
        __syncthreads();
    }
    float inv = 1.0f / fmaxf(sqrtf(red[0]), 1e-12f);
    out[b * FC0V + j] = r * inv;
}

// ---------------- launch -----------------------------------------------------
extern "C" void kernel_launch(void* const* d_in, const int* in_sizes, int n_in,
                              void* d_out, int out_size)
{
    const float* x      = (const float*)d_in[0];
    const int*   length = (const int*)  d_in[1];
    const float* w1  = (const float*)d_in[2];
    const float* b1  = (const float*)d_in[3];
    const float* g1  = (const float*)d_in[4];
    const float* be1 = (const float*)d_in[5];
    const float* m1  = (const float*)d_in[6];
    const float* v1  = (const float*)d_in[7];
    const float* w2  = (const float*)d_in[8];
    const float* b2  = (const float*)d_in[9];
    const float* g2  = (const float*)d_in[10];
    const float* be2 = (const float*)d_in[11];
    const float* m2  = (const float*)d_in[12];
    const float* v2  = (const float*)d_in[13];
    const float* fcw = (const float*)d_in[14];
    const float* fcb = (const float*)d_in[15];
    const float* g3  = (const float*)d_in[16];
    const float* be3 = (const float*)d_in[17];
    const float* m3  = (const float*)d_in[18];
    const float* v3  = (const float*)d_in[19];
    float* out = (float*)d_out;

    cudaFuncSetAttribute(fused2_kernel,
                         cudaFuncAttributeMaxDynamicSharedMemorySize, 187392);

    prep_kernel<<<512, 256>>>(x, length, w1, b1, g1, be1, m1, v1,
                              w2, b2, g2, be2, m2, v2);
    gemm1_kernel<<<NPTS / 128, 512>>>();
    fused2_kernel<<<dim3(18, 8), 512, 187392>>>();
    norm_kernel<<<(BSEG * KCH * CIN) / 256, 256>>>(length);
    fc_kernel<<<dim3(FC0V / 8, 16), 256>>>(fcw);
    final_kernel<<<BSEG, 256>>>(fcb, g3, be3, m3, v3, out);
}

// round 7
// speedup vs baseline: 7.0260x; 1.3832x over previous
#include <cuda_runtime.h>
#include <cuda_fp16.h>
#include <math.h>
#include <stdint.h>

// Shapes (fixed by the problem)
#define NPTS  32768
#define CIN   32
#define FC0V  256
#define KCH   1024
#define BSEG  16
#define BN_EPS 1e-5f
#define LOG2E_F 1.44269504088896340736f

// ---------------- scratch (device globals; no allocations allowed) ----------
__device__ __half g_att1h[(size_t)NPTS * FC0V];        // 16 MB  fp16 att1
__device__ __half g_w2h[(size_t)KCH * FC0V];           // 512 KB fp16 w2
__device__ __half g_w1h[FC0V * CIN];                   // 16 KB  fp16 w1
__device__ __half g_xh[(size_t)NPTS * 40];             // 2.6 MB fp16 [x | 1 | 0pad]
__device__ float  g_sc1[FC0V], g_bias1[FC0V];
__device__ float  g_sc2[KCH],  g_bias2[KCH];
__device__ float  g_poolsum[(size_t)BSEG * KCH * 40];  // 2.6 MB (col 32 = esum)
__device__ float  g_pooled[(size_t)BSEG * KCH * CIN];  // 2 MB
__device__ float  g_outraw[BSEG * FC0V];
__device__ int    g_offsets[BSEG + 1];

// ---------------- helpers ----------------------------------------------------
__device__ __forceinline__ uint32_t smem_u32(const void* p) {
    uint32_t a;
    asm("{ .reg .u64 t; cvta.to.shared.u64 t, %1; cvt.u32.u64 %0, t; }"
        : "=r"(a) : "l"(p));
    return a;
}

#define LDMATRIX_X4(r, addr) \
    asm volatile("ldmatrix.sync.aligned.m8n8.x4.shared.b16 {%0,%1,%2,%3}, [%4];" \
        : "=r"((r)[0]), "=r"((r)[1]), "=r"((r)[2]), "=r"((r)[3]) : "r"(addr))

#define LDMATRIX_X4T(r, addr) \
    asm volatile("ldmatrix.sync.aligned.m8n8.x4.trans.shared.b16 {%0,%1,%2,%3}, [%4];" \
        : "=r"((r)[0]), "=r"((r)[1]), "=r"((r)[2]), "=r"((r)[3]) : "r"(addr))

#define LDMATRIX_X2T(r, addr) \
    asm volatile("ldmatrix.sync.aligned.m8n8.x2.trans.shared.b16 {%0,%1}, [%2];" \
        : "=r"((r)[0]), "=r"((r)[1]) : "r"(addr))

#define MMA_16816(d, a, b0, b1) \
    asm volatile("mma.sync.aligned.m16n8k16.row.col.f32.f16.f16.f32 " \
        "{%0,%1,%2,%3}, {%4,%5,%6,%7}, {%8,%9}, {%0,%1,%2,%3};" \
        : "+f"((d)[0]), "+f"((d)[1]), "+f"((d)[2]), "+f"((d)[3]) \
        : "r"((a)[0]), "r"((a)[1]), "r"((a)[2]), "r"((a)[3]), "r"(b0), "r"(b1))

#define CP_ASYNC16(dst, src) \
    asm volatile("cp.async.cg.shared.global [%0], [%1], 16;" :: "r"(dst), "l"(src))
#define CP_COMMIT() asm volatile("cp.async.commit_group;" ::: "memory")
#define CP_WAIT1()  asm volatile("cp.async.wait_group 1;" ::: "memory")
#define CP_WAIT0()  asm volatile("cp.async.wait_group 0;" ::: "memory")

__device__ __forceinline__ uint32_t h2_exp2(uint32_t v) {
    uint32_t r;
    asm("ex2.approx.f16x2 %0, %1;" : "=r"(r) : "r"(v));
    return r;
}

// ---------------- prep -------------------------------------------------------
__global__ void prep_kernel(const float* __restrict__ x,
                            const int* __restrict__ length,
                            const float* __restrict__ w1, const float* __restrict__ b1,
                            const float* __restrict__ g1, const float* __restrict__ be1,
                            const float* __restrict__ m1, const float* __restrict__ v1,
                            const float* __restrict__ w2, const float* __restrict__ b2,
                            const float* __restrict__ g2, const float* __restrict__ be2,
                            const float* __restrict__ m2, const float* __restrict__ v2) {
    int gid = blockIdx.x * blockDim.x + threadIdx.x;
    int stride = gridDim.x * blockDim.x;
    for (int i = gid; i < BSEG * KCH * 40; i += stride) g_poolsum[i] = 0.0f;
    for (int i = gid; i < BSEG * FC0V; i += stride)     g_outraw[i] = 0.0f;
    for (int i = gid; i < KCH * FC0V; i += stride)      g_w2h[i] = __float2half(w2[i]);
    for (int i = gid; i < FC0V * CIN; i += stride)      g_w1h[i] = __float2half(w1[i]);
    // coalesced [x | 1 | 0] fill: job = (row n, 8-half chunk c8)
    for (int j = gid; j < NPTS * 5; j += stride) {
        int n = j / 5, c8 = j % 5;
        uint4 u;
        __half2* hp = (__half2*)&u;
        if (c8 < 4) {
            const float4* xp = (const float4*)(x + (size_t)n * CIN + c8 * 8);
            float4 v0 = xp[0], v1 = xp[1];
            hp[0] = __floats2half2_rn(v0.x, v0.y);
            hp[1] = __floats2half2_rn(v0.z, v0.w);
            hp[2] = __floats2half2_rn(v1.x, v1.y);
            hp[3] = __floats2half2_rn(v1.z, v1.w);
        } else {
            hp[0] = __floats2half2_rn(1.0f, 0.0f);
            hp[1] = __floats2half2_rn(0.0f, 0.0f);
            hp[2] = hp[1]; hp[3] = hp[1];
        }
        *(uint4*)(g_xh + (size_t)n * 40 + c8 * 8) = u;
    }
    for (int j = gid; j < FC0V; j += stride) {
        float sc = g1[j] * rsqrtf(v1[j] + BN_EPS);
        g_sc1[j]   = sc;
        g_bias1[j] = (b1[j] - m1[j]) * sc + be1[j];
    }
    for (int j = gid; j < KCH; j += stride) {
        float sc = g2[j] * rsqrtf(v2[j] + BN_EPS);
        g_sc2[j]   = sc * LOG2E_F;
        g_bias2[j] = ((b2[j] - m2[j]) * sc + be2[j]) * LOG2E_F;
    }
    if (gid == 0) {
        int s = 0;
        for (int b = 0; b < BSEG; ++b) { g_offsets[b] = s; s += length[b]; }
        g_offsets[BSEG] = s;
    }
}

// ---------------- GEMM1 (HMMA): att1h = fp16(relu(bn1(x @ w1^T + b1))) -------
__global__ void __launch_bounds__(512) gemm1_kernel()
{
    __shared__ __half xs[128 * 40];
    __shared__ __half ws[256 * 40];
    __shared__ float  ssc[256], sbia[256];

    int tid = threadIdx.x, lane = tid & 31, wid = tid >> 5;
    int n0 = blockIdx.x * 128;
    uint32_t xsB = smem_u32(xs), wsB = smem_u32(ws);

    {
        int row = tid >> 2, c = tid & 3;
        CP_ASYNC16(xsB + (uint32_t)(row * 80 + c * 16),
                   g_xh + (size_t)(n0 + row) * 40 + c * 8);
    }
#pragma unroll
    for (int it = 0; it < 2; ++it) {
        int idx = tid + 512 * it;
        int row = idx >> 2, c = idx & 3;
        CP_ASYNC16(wsB + (uint32_t)(row * 80 + c * 16), g_w1h + row * 32 + c * 8);
    }
    if (tid < 256) { ssc[tid] = g_sc1[tid]; sbia[tid] = g_bias1[tid]; }
    CP_COMMIT(); CP_WAIT0(); __syncthreads();

    int warp_m = (wid & 3) * 32, warp_n = (wid >> 2) * 64;
    int lrow = lane & 15, lhi = (lane >> 4) * 16;

    float acc[2][8][4];
#pragma unroll
    for (int mf = 0; mf < 2; ++mf)
#pragma unroll
        for (int n8 = 0; n8 < 8; ++n8)
#pragma unroll
            for (int q = 0; q < 4; ++q) acc[mf][n8][q] = 0.0f;

#pragma unroll
    for (int ks = 0; ks < 2; ++ks) {
        int kbyte = ks * 32 + lhi;
        uint32_t a[2][4], bm[4][4];
#pragma unroll
        for (int mf = 0; mf < 2; ++mf)
            LDMATRIX_X4(a[mf], xsB + (uint32_t)((warp_m + mf * 16 + lrow) * 80 + kbyte));
#pragma unroll
        for (int nf = 0; nf < 4; ++nf)
            LDMATRIX_X4(bm[nf], wsB + (uint32_t)((warp_n + nf * 16 + lrow) * 80 + kbyte));
#pragma unroll
        for (int mf = 0; mf < 2; ++mf)
#pragma unroll
            for (int n8 = 0; n8 < 8; ++n8)
                MMA_16816(acc[mf][n8], a[mf],
                          bm[n8 >> 1][n8 & 1], bm[n8 >> 1][(n8 & 1) + 2]);
    }

    int qrow = lane >> 2, qcol = (lane & 3) * 2;
#pragma unroll
    for (int mf = 0; mf < 2; ++mf)
#pragma unroll
        for (int n8 = 0; n8 < 8; ++n8) {
            int col = warp_n + n8 * 8 + qcol;
            float sc0 = ssc[col], sc1 = ssc[col + 1];
            float bi0 = sbia[col], bi1 = sbia[col + 1];
#pragma unroll
            for (int hh = 0; hh < 2; ++hh) {
                int row = n0 + warp_m + mf * 16 + qrow + hh * 8;
                float t0 = fmaf(acc[mf][n8][hh * 2],     sc0, bi0);
                float t1 = fmaf(acc[mf][n8][hh * 2 + 1], sc1, bi1);
                *(__half2*)(g_att1h + (size_t)row * FC0V + col) =
                    __floats2half2_rn(t0 > 0.f ? t0 : 0.f, t1 > 0.f ? t1 : 0.f);
            }
        }
}

// ---------------- fused GEMM2 + pool (512 thr, 1 CTA/SM) ---------------------
// grid (18, 8). CTA tile 128 rows x 128 ch, K=256 in 2 halves (A double-buf).
// Pool of block i-1 overlaps gemm2-K0 of block i (disjoint smem).
// dyn smem (187,392 B): B@0 (64K) | A@65536 (2x32K) | Et@131072 (34816)
//                       | Xt@165888 (2x10240) | sc@186368 | bias@186880
__global__ void __launch_bounds__(512, 1) fused2_kernel()
{
    extern __shared__ char dyn[];
    float* s_sc = (float*)(dyn + 186368);
    float* s_bi = (float*)(dyn + 186880);

    int tid = threadIdx.x, lane = tid & 31, wid = tid >> 5;
    int cid = blockIdx.x, kt = blockIdx.y;

    int blocks0 = cid * 14 + min(cid, 4);
    int nblk    = 14 + (cid < 4 ? 1 : 0);
    int cs      = blocks0 * 128;

    uint32_t bBase = smem_u32(dyn);
    uint32_t aBase = bBase + 65536u;
    uint32_t eBase = bBase + 131072u;
    uint32_t xBase = bBase + 165888u;

    int warp_m = (wid & 3) * 32, warp_n = (wid >> 2) * 32;
    int lrow = lane & 15, lhi = (lane >> 4) * 16;
    int qrow = lane >> 2, qcol = (lane & 3) * 2;

    int g = lane >> 3, l = lane & 7;
    int wgk = wid >> 3;
    int wch = wid & 7;
    int a_colp = wch * 16 + (g & 1) * 8;
    int a_rowp = (g >> 1) * 8 + l;
    int b_rowp = (g & 1) * 8 + l;
    int b_coff = (g >> 1) * 8;
    int b2_rowp = ((lane >> 3) & 1) * 8 + l;

    auto stageA = [&](int rowg, int h, int buf) {
#pragma unroll
        for (int it = 0; it < 4; ++it) {
            int idx = tid + 512 * it;
            int chunk = idx >> 10;
            int row = (idx >> 3) & 127;
            int c8 = idx & 7;
            uint32_t off = (uint32_t)(row * 128 + c8 * 16);
            CP_ASYNC16(aBase + (uint32_t)buf * 32768u + (uint32_t)chunk * 16384u
                           + (off ^ ((off >> 3) & 0x70)),
                       g_att1h + (size_t)(rowg + row) * FC0V + h * 128 + chunk * 64 + c8 * 8);
        }
    };
    auto stageX = [&](int rowg, int buf) {
#pragma unroll
        for (int it = 0; it < 2; ++it) {
            int idx = tid + 512 * it;
            if (idx < 640) {
                int row = idx / 5, c8 = idx % 5;
                CP_ASYNC16(xBase + (uint32_t)buf * 10240u + (uint32_t)(row * 80 + c8 * 16),
                           g_xh + (size_t)(rowg + row) * 40 + c8 * 8);
            }
        }
    };
    auto gemm2half = [&](int h, int abuf, float (*acc)[4][4]) {
#pragma unroll
        for (int ks = 0; ks < 8; ++ks) {
            int chunk = ks >> 2;
            int kbyte = (ks & 3) * 32 + lhi;
            uint32_t a[2][4], bm[2][4];
#pragma unroll
            for (int mf = 0; mf < 2; ++mf) {
                uint32_t off = (uint32_t)((warp_m + mf * 16 + lrow) * 128);
                LDMATRIX_X4(a[mf], aBase + (uint32_t)abuf * 32768u
                                 + (uint32_t)chunk * 16384u
                                 + ((off + kbyte) ^ ((off >> 3) & 0x70)));
            }
#pragma unroll
            for (int nf = 0; nf < 2; ++nf) {
                uint32_t off = (uint32_t)((warp_n + nf * 16 + lrow) * 128);
                LDMATRIX_X4(bm[nf], bBase + (uint32_t)(h * 2 + chunk) * 16384u
                                  + ((off + kbyte) ^ ((off >> 3) & 0x70)));
            }
#pragma unroll
            for (int mf = 0; mf < 2; ++mf)
#pragma unroll
                for (int n8 = 0; n8 < 4; ++n8)
                    MMA_16816(acc[mf][n8], a[mf],
                              bm[n8 >> 1][n8 & 1], bm[n8 >> 1][(n8 & 1) + 2]);
        }
    };
    auto epilogue = [&](float (*acc)[4][4]) {
#pragma unroll
        for (int mf = 0; mf < 2; ++mf)
#pragma unroll
            for (int n8 = 0; n8 < 4; ++n8) {
                int col = warp_n + n8 * 8 + qcol;
                float sc0 = s_sc[col], sc1 = s_sc[col + 1];
                float bi0 = s_bi[col], bi1 = s_bi[col + 1];
#pragma unroll
                for (int hh = 0; hh < 2; ++hh) {
                    int row = warp_m + mf * 16 + qrow + hh * 8;
                    float t0 = fmaf(acc[mf][n8][hh * 2],     sc0, bi0);
                    float t1 = fmaf(acc[mf][n8][hh * 2 + 1], sc1, bi1);
                    __half2 th = __floats2half2_rn(t0, t1);
                    th = __hmax2(th, __floats2half2_rn(0.f, 0.f));
                    uint32_t eu = h2_exp2(*(uint32_t*)&th);   // 2^max(t,0); =1 at t<=0
                    *(uint32_t*)(dyn + 131072 + row * 272 + col * 2) = eu;
                }
            }
    };
    auto poolmma = [&](float (*pc)[4], int xbuf) {
        uint32_t xb = xBase + (uint32_t)xbuf * 10240u;
#pragma unroll
        for (int ks = 0; ks < 4; ++ks) {
            int k0 = wgk * 64 + ks * 16;
            uint32_t a[4], b0[4], b1[4], b2[2];
            LDMATRIX_X4T(a,  eBase + (uint32_t)((k0 + a_rowp) * 272 + a_colp * 2));
            LDMATRIX_X4T(b0, xb + (uint32_t)((k0 + b_rowp) * 80 + b_coff * 2));
            LDMATRIX_X4T(b1, xb + (uint32_t)((k0 + b_rowp) * 80 + (16 + b_coff) * 2));
            LDMATRIX_X2T(b2, xb + (uint32_t)((k0 + b2_rowp) * 80 + 64));
            MMA_16816(pc[0], a, b0[0], b0[1]);
            MMA_16816(pc[1], a, b0[2], b0[3]);
            MMA_16816(pc[2], a, b1[0], b1[1]);
            MMA_16816(pc[3], a, b1[2], b1[3]);
            MMA_16816(pc[4], a, b2[0], b2[1]);
        }
    };
    auto flushp = [&](float (*pc)[4], int seg) {
        float* ps = g_poolsum + (size_t)seg * (KCH * 40);
        int row0 = kt * 128 + wch * 16 + (lane >> 2);
        int col0 = (lane & 3) * 2;
#pragma unroll
        for (int t = 0; t < 5; ++t) {
            int c = t * 8 + col0;
            atomicAdd(&ps[(size_t)row0 * 40 + c],           pc[t][0]);
            atomicAdd(&ps[(size_t)row0 * 40 + c + 1],       pc[t][1]);
            atomicAdd(&ps[(size_t)(row0 + 8) * 40 + c],     pc[t][2]);
            atomicAdd(&ps[(size_t)(row0 + 8) * 40 + c + 1], pc[t][3]);
#pragma unroll
            for (int q = 0; q < 4; ++q) pc[t][q] = 0.0f;
        }
    };
    auto maskX = [&](int rowg, int xbuf, int ra, int rb, bool load) {
#pragma unroll
        for (int it = 0; it < 2; ++it) {
            int idx = tid + 512 * it;
            if (idx < 640) {
                int row = idx / 5, c8 = idx % 5;
                if (row >= ra && row < rb) {
                    uint4 v = make_uint4(0, 0, 0, 0);
                    if (load)
                        v = *(const uint4*)(g_xh + (size_t)(rowg + row) * 40 + c8 * 8);
                    *(uint4*)(dyn + 165888 + xbuf * 10240 + row * 80 + c8 * 16) = v;
                }
            }
        }
    };

    int bp = 0;   // pool segment cursor
    float pacc[5][4];
#pragma unroll
    for (int t = 0; t < 5; ++t)
#pragma unroll
        for (int q = 0; q < 4; ++q) pacc[t][q] = 0.0f;

    // pool one 128-row block at rows [r0p, r0p+128) from Et using X buffer xb
    auto poolstep = [&](int r0p, int xb) {
        int send = g_offsets[bp + 1];
        if (send >= r0p + 128) {
            poolmma(pacc, xb);
            if (send == r0p + 128) { flushp(pacc, bp); ++bp; }
        } else {
            int rbnd = send - r0p;               // 1..127
            maskX(r0p, xb, rbnd, 128, false);
            __syncthreads();
            poolmma(pacc, xb);
            flushp(pacc, bp); ++bp;
            __syncthreads();
            maskX(r0p, xb, rbnd, 128, true);
            maskX(r0p, xb, 0, rbnd, false);
            __syncthreads();
            poolmma(pacc, xb);
        }
    };

    // prologue
#pragma unroll
    for (int it = 0; it < 8; ++it) {
        int idx = tid + 512 * it;
        int chunk = idx >> 10;
        int row = (idx >> 3) & 127;
        int c8 = idx & 7;
        uint32_t off = (uint32_t)(row * 128 + c8 * 16);
        CP_ASYNC16(bBase + (uint32_t)chunk * 16384u + (off ^ ((off >> 3) & 0x70)),
                   g_w2h + (size_t)(kt * 128 + row) * FC0V + chunk * 64 + c8 * 8);
    }
    stageA(cs, 0, 0);
    stageX(cs, 0);
    if (tid < 128) {
        s_sc[tid] = g_sc2[kt * 128 + tid];
        s_bi[tid] = g_bias2[kt * 128 + tid];
    }
    CP_COMMIT();
    stageA(cs, 1, 1);
    CP_COMMIT();

    while (g_offsets[bp + 1] <= cs) ++bp;

    for (int blk = 0; blk < nblk; ++blk) {
        int r0 = cs + blk * 128;
        bool more = (blk + 1 < nblk);

        CP_WAIT1();                 // A(blk,h0) ready (+B,X on blk 0)
        __syncthreads();

        float acc[2][4][4];
#pragma unroll
        for (int mf = 0; mf < 2; ++mf)
#pragma unroll
            for (int n8 = 0; n8 < 4; ++n8)
#pragma unroll
                for (int q = 0; q < 4; ++q) acc[mf][n8][q] = 0.0f;

        // Phase 1: gemm2 K-half 0 of blk + pool of blk-1 (disjoint smem)
        gemm2half(0, 0, acc);
        if (blk > 0) poolstep(r0 - 128, (blk - 1) & 1);
        __syncthreads();            // Abuf0 reads + Et(blk-1) reads done
        if (more) stageA(r0 + 128, 0, 0);
        CP_COMMIT();
        CP_WAIT1();                 // A(blk,h1) ready
        __syncthreads();

        // Phase 2: gemm2 K-half 1 + epilogue -> Et
        gemm2half(1, 1, acc);
        epilogue(acc);
        __syncthreads();            // Et written; Abuf1 reads done
        if (more) { stageA(r0 + 128, 1, 1); stageX(r0 + 128, (blk + 1) & 1); }
        CP_COMMIT();
    }
    // tail: pool last block, flush remainder
    poolstep(cs + (nblk - 1) * 128, (nblk - 1) & 1);
    flushp(pacc, min(bp, BSEG - 1));
}

// ---------------- normalize: pooled[b,k,c] = ps[b,k,c] / (ps[b,k,32]*len) ----
__global__ void norm_kernel(const int* __restrict__ length) {
    int idx = blockIdx.x * 256 + threadIdx.x;
    int c = idx & 31, k = (idx >> 5) & 1023, b = idx >> 15;
    const float* ps = g_poolsum + ((size_t)b * KCH + k) * 40;
    g_pooled[idx] = ps[c] / (ps[32] * (float)length[b]);
}

// ---------------- FC: out_raw[b,j] += pooled[b,:] . fcw[j,:]  (split-K) ------
__global__ void __launch_bounds__(256) fc_kernel(const float* __restrict__ fcw)
{
    int warp = threadIdx.x >> 5, lane = threadIdx.x & 31;
    int j  = blockIdx.x * 8 + warp;
    int i0 = blockIdx.y * 2048;

    float acc[BSEG];
#pragma unroll
    for (int b = 0; b < BSEG; ++b) acc[b] = 0.0f;

    const float4* fw4 = (const float4*)(fcw + (size_t)j * (KCH * CIN) + i0);
#pragma unroll 4
    for (int it = 0; it < 16; ++it) {
        int i4 = it * 32 + lane;
        float4 f = fw4[i4];
#pragma unroll
        for (int b = 0; b < BSEG; ++b) {
            float4 p = ((const float4*)(g_pooled + (size_t)b * (KCH * CIN) + i0))[i4];
            acc[b] += f.x * p.x + f.y * p.y + f.z * p.z + f.w * p.w;
        }
    }
#pragma unroll
    for (int b = 0; b < BSEG; ++b) {
        float v = acc[b];
#pragma unroll
        for (int s = 16; s > 0; s >>= 1) v += __shfl_xor_sync(0xffffffffu, v, s);
        if (lane == 0) atomicAdd(&g_outraw[b * FC0V + j], v);
    }
}

// ---------------- final: BN3 + row L2-normalize -> d_out [16,256] ------------
__global__ void final_kernel(
    const float* __restrict__ fcb, const float* __restrict__ g3,
    const float* __restrict__ be3, const float* __restrict__ m3,
    const float* __restrict__ v3,  float* __restrict__ out)
{
    int b = blockIdx.x, j = threadIdx.x;
    float sc = g3[j] * rsqrtf(v3[j] + BN_EPS);
    float r  = fmaf(g_outraw[b * FC0V + j] + fcb[j] - m3[j], sc, be3[j]);

    __shared__ float red[256];
    red[j] = r * r;
    __syncthreads();
    for (int s = 128; s > 0; s >>= 1) {
        if (j < s) red[j] += red[j + s];
        __syncthreads();
    }
    float inv = 1.0f / fmaxf(sqrtf(red[0]), 1e-12f);
    out[b * FC0V + j] = r * inv;
}

// ---------------- launch -----------------------------------------------------
extern "C" void kernel_launch(void* const* d_in, const int* in_sizes, int n_in,
                              void* d_out, int out_size)
{
    const float* x      = (const float*)d_in[0];
    const int*   length = (const int*)  d_in[1];
    const float* w1  = (const float*)d_in[2];
    const float* b1  = (const float*)d_in[3];
    const float* g1  = (const float*)d_in[4];
    const float* be1 = (const float*)d_in[5];
    const float* m1  = (const float*)d_in[6];
    const float* v1  = (const float*)d_in[7];
    const float* w2  = (const float*)d_in[8];
    const float* b2  = (const float*)d_in[9];
    const float* g2  = (const float*)d_in[10];
    const float* be2 = (const float*)d_in[11];
    const float* m2  = (const float*)d_in[12];
    const float* v2  = (const float*)d_in[13];
    const float* fcw = (const float*)d_in[14];
    const float* fcb = (const float*)d_in[15];
    const float* g3  = (const float*)d_in[16];
    const float* be3 = (const float*)d_in[17];
    const float* m3  = (const float*)d_in[18];
    const float* v3  = (const float*)d_in[19];
    float* out = (float*)d_out;

    cudaFuncSetAttribute(fused2_kernel,
                         cudaFuncAttributeMaxDynamicSharedMemorySize, 187392);

    prep_kernel<<<512, 256>>>(x, length, w1, b1, g1, be1, m1, v1,
                              w2, b2, g2, be2, m2, v2);
    gemm1_kernel<<<NPTS / 128, 512>>>();
    fused2_kernel<<<dim3(18, 8), 512, 187392>>>();
    norm_kernel<<<(BSEG * KCH * CIN) / 256, 256>>>(length);
    fc_kernel<<<dim3(FC0V / 8, 16), 256>>>(fcw);
    final_kernel<<<BSEG, 256>>>(fcb, g3, be3, m3, v3, out);
}